// round 11
// baseline (speedup 1.0000x reference)
#include <cuda_runtime.h>
#include <math.h>
#include <cstdint>

#define B_TOT   32768
#define T_STEPS 32
#define HID     128
#define OBS_OS  8
#define OBS_TS  6
#define SDIM    200
#define NACT    9
#define M_TILE  32
#define NTHREADS 256
#define NCTA    (B_TOT / M_TILE)

typedef unsigned long long u64;

// ---------------- scratch ----------------
__device__ int   g_nobs[B_TOT];
__device__ int   g_perm[B_TOT];
__device__ int   g_hist[T_STEPS + 1];
__device__ int   g_cursor[T_STEPS + 1];
__device__ float g_hout[B_TOT * HID];     // h snapshot (16 MB static scratch)

// ---------------- shared layout (float offsets), total 28656 fl = 111.9 KB ----------------
#define O_BUFA  0                  // W chunk buf A [512][20] (16 K + pad)
#define O_BUFB  10240              // W chunk buf B [512][20]
#define O_WIH   20480              // W_ih [512][6] packed (same layout as gmem)
#define O_HT    23552              // hT [k=128][36] (m contiguous)
#define O_SX    28160              // xT double buffer 2 x [6][36]
#define O_INT   28592              // nobs[32], samp[32]
#define SMEM_FLOATS 28656
#define SMEM_BYTES  (SMEM_FLOATS * 4)
// head overlays (all below O_SX, sSamp/sNobs preserved)
#define O_WTS   0                  // [128][132] = 16896
#define O_XCAT  16896              // [32][256] = 8192   (C1 overlays this after sync)
#define O_WC2   25088              // [9][132]  = 1188 -> 26276
#define O_C1    O_XCAT

// ---------------- helpers ----------------
__device__ __forceinline__ unsigned smem_u32(const void* p) {
    unsigned r;
    asm("{ .reg .u64 t; cvta.to.shared.u64 t, %1; cvt.u32.u64 %0, t; }" : "=r"(r) : "l"(p));
    return r;
}
__device__ __forceinline__ void cpa16(unsigned dst, const void* src) {
    asm volatile("cp.async.cg.shared.global [%0], [%1], 16;" :: "r"(dst), "l"(src));
}
__device__ __forceinline__ void cpa4(unsigned dst, const void* src) {
    asm volatile("cp.async.ca.shared.global [%0], [%1], 4;" :: "r"(dst), "l"(src));
}
#define CP_COMMIT()  asm volatile("cp.async.commit_group;" ::: "memory")
#define CP_WAIT1()   asm volatile("cp.async.wait_group 1;" ::: "memory")
#define CP_WAIT0()   asm volatile("cp.async.wait_group 0;" ::: "memory")

__device__ __forceinline__ void fma2(u64 &d, u64 a, u64 b) {
    asm("fma.rn.f32x2 %0, %1, %2, %0;" : "+l"(d) : "l"(a), "l"(b));
}
__device__ __forceinline__ u64 dup2(float a) {
    u64 r; asm("mov.b64 %0, {%1, %1};" : "=l"(r) : "f"(a)); return r;
}
__device__ __forceinline__ void unp2(u64 v, float &lo, float &hi) {
    asm("mov.b64 {%0, %1}, %2;" : "=f"(lo), "=f"(hi) : "l"(v));
}
__device__ __forceinline__ float tanhfast(float x) {
    float y; asm("tanh.approx.f32 %0, %1;" : "=f"(y) : "f"(x)); return y;
}
__device__ __forceinline__ float sigfast(float x) {
    return fmaf(tanhfast(0.5f * x), 0.5f, 0.5f);
}

// ---------------- pre-pass ----------------
__global__ void k_count(const float* __restrict__ s) {
    int m = blockIdx.x * blockDim.x + threadIdx.x;
    if (m >= B_TOT) return;
    const float* p = s + m * SDIM + OBS_OS;
    int cnt = 0;
#pragma unroll
    for (int t = 0; t < T_STEPS; ++t) {
        float v = p[t * OBS_TS];
        cnt += (v == v) ? 1 : 0;
    }
    g_nobs[m] = cnt;
    atomicAdd(&g_hist[cnt], 1);
    if (cnt == 0) {   // reference: x_TS input forced to 0 for empty sequences
        float4 z = make_float4(0.f, 0.f, 0.f, 0.f);
        float4* d = (float4*)(g_hout + m * HID);
#pragma unroll
        for (int q = 0; q < HID / 4; ++q) d[q] = z;
    }
}

__global__ void k_prefix() {
    int off = 0;
    for (int len = T_STEPS; len >= 0; --len) {
        g_cursor[len] = off;
        off += g_hist[len];
        g_hist[len] = 0;
    }
}

__global__ void k_scatter() {
    int m = blockIdx.x * blockDim.x + threadIdx.x;
    if (m >= B_TOT) return;
    int pos = atomicAdd(&g_cursor[g_nobs[m]], 1);
    g_perm[pos] = m;
}

// ---------------- fused main kernel ----------------
__global__ void __launch_bounds__(NTHREADS, 2)
k_main(const float* __restrict__ s,
       const float* __restrict__ W_os, const float* __restrict__ b_os,
       const float* __restrict__ W_ih, const float* __restrict__ W_hh,
       const float* __restrict__ b_ih, const float* __restrict__ b_hh,
       const float* __restrict__ W_ts, const float* __restrict__ b_ts,
       const float* __restrict__ W_c1, const float* __restrict__ b_c1,
       const float* __restrict__ W_c2, const float* __restrict__ b_c2,
       float* __restrict__ out)
{
    extern __shared__ float sm[];
    float* bufA  = sm + O_BUFA;
    float* bufB  = sm + O_BUFB;
    float* sWih  = sm + O_WIH;
    float* hT    = sm + O_HT;
    float* sX    = sm + O_SX;
    int*   sNobs = (int*)(sm + O_INT);
    int*   sSamp = sNobs + M_TILE;
    __shared__ int sTmaxS;

    const unsigned uBufA = smem_u32(bufA);
    const unsigned uBufB = smem_u32(bufB);
    const unsigned uSX   = smem_u32(sX);

    const int tid = threadIdx.x;
    const int jh  = tid & 127;    // hidden unit (owns gate rows jh+128g)
    const int mg  = tid >> 7;     // sample half: 16 samples mg*16..+15
    const int base = blockIdx.x * M_TILE;

    if (tid < M_TILE) {
        int idx = g_perm[base + tid];
        sSamp[tid] = idx;
        sNobs[tid] = g_nobs[idx];
    }
    __syncthreads();

    // prologue prefetch: group0 = chunk0 + xT(0); group1 = chunk1
#pragma unroll
    for (int q = 0; q < 8; ++q) {
        int lin = q * NTHREADS + tid;       // 0..2047 float4s
        int r = lin >> 2, cc = lin & 3;
        cpa16(uBufA + (unsigned)(r * 20 + cc * 4) * 4u,
              W_hh + r * HID + 0 * 16 + cc * 4);
    }
    if (tid < M_TILE * OBS_TS) {
        int m = tid / OBS_TS, i = tid - m * OBS_TS;
        cpa4(uSX + (unsigned)(i * 36 + m) * 4u,
             s + sSamp[m] * SDIM + OBS_OS + 0 * OBS_TS + i);
    }
    CP_COMMIT();
#pragma unroll
    for (int q = 0; q < 8; ++q) {
        int lin = q * NTHREADS + tid;
        int r = lin >> 2, cc = lin & 3;
        cpa16(uBufB + (unsigned)(r * 20 + cc * 4) * 4u,
              W_hh + r * HID + 1 * 16 + cc * 4);
    }
    CP_COMMIT();

    // stage W_ih (identical layout -> straight copy) + zero hT while prefetch flies
    for (int i = tid; i < 512 * OBS_TS; i += NTHREADS) sWih[i] = W_ih[i];
    for (int i = tid; i < 128 * 36; i += NTHREADS) hT[i] = 0.0f;
    if (tid == 0) {
        int tm = 0;
        for (int m = 0; m < M_TILE; ++m) tm = max(tm, sNobs[m]);
        sTmaxS = tm;
    }

    float biasv[4];
#pragma unroll
    for (int g = 0; g < 4; ++g)
        biasv[g] = b_ih[jh + 128 * g] + b_hh[jh + 128 * g];
    float creg[16];
#pragma unroll
    for (int e = 0; e < 16; ++e) creg[e] = 0.0f;

    __syncthreads();
    const int tmax = sTmaxS;

    // ================= LSTM recurrence =================
    for (int t = 0; t < tmax; ++t) {
        float* xTc = sX + (t & 1) * 216;

        u64 aI[8], aF[8], aG[8], aO[8];   // 8 m-pairs each (16 samples)
        {
            u64 bi = dup2(biasv[0]), bf = dup2(biasv[1]);
            u64 bg = dup2(biasv[2]), bo = dup2(biasv[3]);
#pragma unroll
            for (int p = 0; p < 8; ++p) { aI[p] = bi; aF[p] = bf; aG[p] = bg; aO[p] = bo; }
        }

#pragma unroll 2
        for (int c = 0; c < 8; ++c) {
            CP_WAIT1();
            __syncthreads();            // chunk c visible; prev buf readers done; hT published

            if (c == 0) {
                // sanitize xT(t): NaN -> 0 (consumed at c==1 after its barrier)
                if (tid < M_TILE * OBS_TS) {
                    int m = tid / OBS_TS, i = tid - m * OBS_TS;
                    float v = xTc[i * 36 + m];
                    xTc[i * 36 + m] = (v == v) ? v : 0.0f;
                }
            }
            if (c == 1) {
                // x contribution
#pragma unroll
                for (int i = 0; i < OBS_TS; ++i) {
                    u64 wi = dup2(sWih[(jh      ) * 6 + i]);
                    u64 wf = dup2(sWih[(jh + 128) * 6 + i]);
                    u64 wg = dup2(sWih[(jh + 256) * 6 + i]);
                    u64 wo = dup2(sWih[(jh + 384) * 6 + i]);
                    const ulonglong2* xp = (const ulonglong2*)(xTc + i * 36 + mg * 16);
                    ulonglong2 x01 = xp[0], x23 = xp[1], x45 = xp[2], x67 = xp[3];
                    fma2(aI[0], wi, x01.x); fma2(aI[1], wi, x01.y);
                    fma2(aI[2], wi, x23.x); fma2(aI[3], wi, x23.y);
                    fma2(aI[4], wi, x45.x); fma2(aI[5], wi, x45.y);
                    fma2(aI[6], wi, x67.x); fma2(aI[7], wi, x67.y);
                    fma2(aF[0], wf, x01.x); fma2(aF[1], wf, x01.y);
                    fma2(aF[2], wf, x23.x); fma2(aF[3], wf, x23.y);
                    fma2(aF[4], wf, x45.x); fma2(aF[5], wf, x45.y);
                    fma2(aF[6], wf, x67.x); fma2(aF[7], wf, x67.y);
                    fma2(aG[0], wg, x01.x); fma2(aG[1], wg, x01.y);
                    fma2(aG[2], wg, x23.x); fma2(aG[3], wg, x23.y);
                    fma2(aG[4], wg, x45.x); fma2(aG[5], wg, x45.y);
                    fma2(aG[6], wg, x67.x); fma2(aG[7], wg, x67.y);
                    fma2(aO[0], wo, x01.x); fma2(aO[1], wo, x01.y);
                    fma2(aO[2], wo, x23.x); fma2(aO[3], wo, x23.y);
                    fma2(aO[4], wo, x45.x); fma2(aO[5], wo, x45.y);
                    fma2(aO[6], wo, x67.x); fma2(aO[7], wo, x67.y);
                }
            }

            const float* buf = (c & 1) ? bufB : bufA;
#pragma unroll 1
            for (int kk = 0; kk < 4; ++kk) {
                float4 wI = *(const float4*)(buf + (jh      ) * 20 + kk * 4);
                float4 wF = *(const float4*)(buf + (jh + 128) * 20 + kk * 4);
                float4 wG = *(const float4*)(buf + (jh + 256) * 20 + kk * 4);
                float4 wO = *(const float4*)(buf + (jh + 384) * 20 + kk * 4);
                const float* hb = hT + (c * 16 + kk * 4) * 36 + mg * 16;
#pragma unroll
                for (int q = 0; q < 4; ++q) {
                    const ulonglong2* hp = (const ulonglong2*)(hb + q * 36);
                    ulonglong2 h01 = hp[0], h23 = hp[1], h45 = hp[2], h67 = hp[3];
                    float wIq = (q == 0) ? wI.x : (q == 1) ? wI.y : (q == 2) ? wI.z : wI.w;
                    float wFq = (q == 0) ? wF.x : (q == 1) ? wF.y : (q == 2) ? wF.z : wF.w;
                    float wGq = (q == 0) ? wG.x : (q == 1) ? wG.y : (q == 2) ? wG.z : wG.w;
                    float wOq = (q == 0) ? wO.x : (q == 1) ? wO.y : (q == 2) ? wO.z : wO.w;
                    u64 wi = dup2(wIq), wf = dup2(wFq), wg = dup2(wGq), wo = dup2(wOq);
                    fma2(aI[0], wi, h01.x); fma2(aI[1], wi, h01.y);
                    fma2(aI[2], wi, h23.x); fma2(aI[3], wi, h23.y);
                    fma2(aI[4], wi, h45.x); fma2(aI[5], wi, h45.y);
                    fma2(aI[6], wi, h67.x); fma2(aI[7], wi, h67.y);
                    fma2(aF[0], wf, h01.x); fma2(aF[1], wf, h01.y);
                    fma2(aF[2], wf, h23.x); fma2(aF[3], wf, h23.y);
                    fma2(aF[4], wf, h45.x); fma2(aF[5], wf, h45.y);
                    fma2(aF[6], wf, h67.x); fma2(aF[7], wf, h67.y);
                    fma2(aG[0], wg, h01.x); fma2(aG[1], wg, h01.y);
                    fma2(aG[2], wg, h23.x); fma2(aG[3], wg, h23.y);
                    fma2(aG[4], wg, h45.x); fma2(aG[5], wg, h45.y);
                    fma2(aG[6], wg, h67.x); fma2(aG[7], wg, h67.y);
                    fma2(aO[0], wo, h01.x); fma2(aO[1], wo, h01.y);
                    fma2(aO[2], wo, h23.x); fma2(aO[3], wo, h23.y);
                    fma2(aO[4], wo, h45.x); fma2(aO[5], wo, h45.y);
                    fma2(aO[6], wo, h67.x); fma2(aO[7], wo, h67.y);
                }
            }
            __syncthreads();            // all reads of this buf + hT done

            // prefetch chunk (c+2)&7 (next step's chunks when wrapping)
            int nc = (c + 2) & 7;
            unsigned ubuf = (c & 1) ? uBufB : uBufA;
#pragma unroll
            for (int q = 0; q < 8; ++q) {
                int lin = q * NTHREADS + tid;
                int r = lin >> 2, cc2 = lin & 3;
                cpa16(ubuf + (unsigned)(r * 20 + cc2 * 4) * 4u,
                      W_hh + r * HID + nc * 16 + cc2 * 4);
            }
            if (c == 6 && (t + 1) < tmax && tid < M_TILE * OBS_TS) {
                int m = tid / OBS_TS, i = tid - m * OBS_TS;
                cpa4(uSX + (unsigned)(((t + 1) & 1) * 216 + i * 36 + m) * 4u,
                     s + sSamp[m] * SDIM + OBS_OS + (t + 1) * OBS_TS + i);
            }
            CP_COMMIT();
        }

        // update: gates for (jh, 16 samples) in registers — no exchange
#pragma unroll
        for (int p = 0; p < 8; ++p) {
            float i0, i1, f0, f1, g0, g1, o0, o1;
            unp2(aI[p], i0, i1);
            unp2(aF[p], f0, f1);
            unp2(aG[p], g0, g1);
            unp2(aO[p], o0, o1);
#pragma unroll
            for (int e = 0; e < 2; ++e) {
                int sloc = p * 2 + e;
                int m = mg * 16 + sloc;
                float gi = e ? i1 : i0, gf = e ? f1 : f0;
                float gg = e ? g1 : g0, go = e ? o1 : o0;
                float iv = sigfast(gi), fv = sigfast(gf);
                float gv = tanhfast(gg), ov = sigfast(go);
                float cv = fmaf(fv, creg[sloc], iv * gv);
                creg[sloc] = cv;
                float hv = ov * tanhfast(cv);
                hT[jh * 36 + m] = hv;
                if (t == sNobs[m] - 1) g_hout[sSamp[m] * HID + jh] = hv;
            }
        }
        // next step's chunk-0 barrier publishes hT
    }

    CP_WAIT0();
    __syncthreads();

    // ================= head =================
    float* sWts  = sm + O_WTS;
    float* sXcat = sm + O_XCAT;
    float* sWc2  = sm + O_WC2;
    float* sC1o  = sm + O_C1;

    // stage W_ts [128][132]
#pragma unroll
    for (int q = 0; q < 17; ++q) {
        int idx = q * NTHREADS + tid;       // float4 index
        if (idx < 128 * 32) {
            int r = idx >> 5, cc = idx & 31;
            *(float4*)(sWts + r * 132 + cc * 4) = *(const float4*)(W_ts + r * HID + cc * 4);
        }
    }
    // stage W_c2 [9][132] — STRIDED (288 float4s > NTHREADS; this was the R7 bug)
    for (int idx = tid; idx < NACT * 32; idx += NTHREADS) {
        int o = idx >> 5, kb = (idx & 31) * 4;
        *(float4*)(sWc2 + o * 132 + kb) = *(const float4*)(W_c2 + o * HID + kb);
    }
    __syncthreads();

    // x_OS = relu(s_OS @ W_os^T + b_os) -> xcat[:, :128] (direct LDG of s_OS)
    {
        float wos[8];
#pragma unroll
        for (int i = 0; i < 8; ++i) wos[i] = W_os[jh * 8 + i];
        float bos = b_os[jh];
#pragma unroll
        for (int mm = 0; mm < 16; ++mm) {
            int m = mg * 16 + mm;
            const float4* sp = (const float4*)(s + sSamp[m] * SDIM);
            float4 s0 = sp[0], s1 = sp[1];
            float a = bos;
            a = fmaf(wos[0], s0.x, a); a = fmaf(wos[1], s0.y, a);
            a = fmaf(wos[2], s0.z, a); a = fmaf(wos[3], s0.w, a);
            a = fmaf(wos[4], s1.x, a); a = fmaf(wos[5], s1.y, a);
            a = fmaf(wos[6], s1.z, a); a = fmaf(wos[7], s1.w, a);
            sXcat[m * 256 + jh] = fmaxf(a, 0.0f);
        }
    }
    // x_TS = relu(hout @ W_ts^T + b_ts) -> xcat[:, 128:]; hout via uniform LDG
    {
        float a16[16];
#pragma unroll
        for (int mm = 0; mm < 16; ++mm) a16[mm] = 0.0f;
#pragma unroll 1
        for (int k4 = 0; k4 < 32; ++k4) {
            float4 w = *(const float4*)(sWts + jh * 132 + k4 * 4);
#pragma unroll
            for (int mm = 0; mm < 16; ++mm) {
                int m = mg * 16 + mm;
                float4 h = *(const float4*)(g_hout + sSamp[m] * HID + k4 * 4);
                float a = a16[mm];
                a = fmaf(w.x, h.x, a);
                a = fmaf(w.y, h.y, a);
                a = fmaf(w.z, h.z, a);
                a = fmaf(w.w, h.w, a);
                a16[mm] = a;
            }
        }
        float bts = b_ts[jh];
#pragma unroll
        for (int mm = 0; mm < 16; ++mm) {
            int m = mg * 16 + mm;
            sXcat[m * 256 + HID + jh] = fmaxf(a16[mm] + bts, 0.0f);
        }
    }
    __syncthreads();

    // c1 = relu(xcat @ W_c1^T + b_c1), K=256 in two staged halves
    {
        float a16[16];
#pragma unroll
        for (int mm = 0; mm < 16; ++mm) a16[mm] = 0.0f;
#pragma unroll 1
        for (int half = 0; half < 2; ++half) {
            __syncthreads();
#pragma unroll
            for (int q = 0; q < 17; ++q) {
                int idx = q * NTHREADS + tid;
                if (idx < 128 * 32) {
                    int r = idx >> 5, cc = idx & 31;
                    *(float4*)(sWts + r * 132 + cc * 4) =
                        *(const float4*)(W_c1 + r * 256 + half * 128 + cc * 4);
                }
            }
            __syncthreads();
#pragma unroll 1
            for (int k4 = 0; k4 < 32; ++k4) {
                float4 w = *(const float4*)(sWts + jh * 132 + k4 * 4);
#pragma unroll
                for (int mm = 0; mm < 16; ++mm) {
                    int m = mg * 16 + mm;
                    float4 x = *(const float4*)(sXcat + m * 256 + half * 128 + k4 * 4);
                    float a = a16[mm];
                    a = fmaf(w.x, x.x, a);
                    a = fmaf(w.y, x.y, a);
                    a = fmaf(w.z, x.z, a);
                    a = fmaf(w.w, x.w, a);
                    a16[mm] = a;
                }
            }
        }
        __syncthreads();   // xcat reads done before C1 overlays it
        float bc1 = b_c1[jh];
#pragma unroll
        for (int mm = 0; mm < 16; ++mm) {
            int m = mg * 16 + mm;
            sC1o[m * 132 + jh] = fmaxf(a16[mm] + bc1, 0.0f);
        }
    }
    __syncthreads();

    // out = c1 @ W_c2^T + b_c2 (288 outputs)
    for (int idx = tid; idx < M_TILE * NACT; idx += NTHREADS) {
        int m = idx / NACT, o = idx - m * NACT;
        float a = b_c2[o];
#pragma unroll 1
        for (int k4 = 0; k4 < 32; ++k4) {
            float4 w = *(const float4*)(sWc2 + o * 132 + k4 * 4);
            float4 x = *(const float4*)(sC1o + m * 132 + k4 * 4);
            a = fmaf(w.x, x.x, a);
            a = fmaf(w.y, x.y, a);
            a = fmaf(w.z, x.z, a);
            a = fmaf(w.w, x.w, a);
        }
        out[sSamp[m] * NACT + o] = a;
    }
}

// ---------------- launch ----------------
extern "C" void kernel_launch(void* const* d_in, const int* in_sizes, int n_in,
                              void* d_out, int out_size) {
    const float* s    = (const float*)d_in[0];
    const float* W_os = (const float*)d_in[1];
    const float* b_os = (const float*)d_in[2];
    const float* W_ih = (const float*)d_in[3];
    const float* W_hh = (const float*)d_in[4];
    const float* b_ih = (const float*)d_in[5];
    const float* b_hh = (const float*)d_in[6];
    const float* W_ts = (const float*)d_in[7];
    const float* b_ts = (const float*)d_in[8];
    const float* W_c1 = (const float*)d_in[9];
    const float* b_c1 = (const float*)d_in[10];
    const float* W_c2 = (const float*)d_in[11];
    const float* b_c2 = (const float*)d_in[12];
    float* out = (float*)d_out;

    cudaFuncSetAttribute(k_main, cudaFuncAttributeMaxDynamicSharedMemorySize, SMEM_BYTES);

    k_count<<<B_TOT / 256, 256>>>(s);
    k_prefix<<<1, 1>>>();
    k_scatter<<<B_TOT / 256, 256>>>();
    k_main<<<NCTA, NTHREADS, SMEM_BYTES>>>(s, W_os, b_os, W_ih, W_hh, b_ih, b_hh,
                                           W_ts, b_ts, W_c1, b_c1, W_c2, b_c2, out);
}

// round 12
// speedup vs baseline: 1.0028x; 1.0028x over previous
#include <cuda_runtime.h>
#include <math.h>
#include <cstdint>

#define B_TOT   32768
#define T_STEPS 32
#define HID     128
#define OBS_OS  8
#define OBS_TS  6
#define SDIM    200
#define NACT    9
#define M_TILE  32
#define NTHREADS 256
#define NCTA    (B_TOT / M_TILE)

typedef unsigned long long u64;

// ---------------- scratch ----------------
__device__ int   g_nobs[B_TOT];
__device__ int   g_perm[B_TOT];
__device__ int   g_hist[T_STEPS + 1];
__device__ int   g_cursor[T_STEPS + 1];
__device__ float g_hout[B_TOT * HID];     // h snapshot (16 MB static scratch)

// ---------------- shared layout (float offsets), total 28656 fl = 111.9 KB ----------------
#define O_BUFA  0                  // W chunk buf A [512][20] (16 K + pad)
#define O_BUFB  10240              // W chunk buf B [512][20]
#define O_WIH   20480              // W_ih [512][6] packed (same layout as gmem)
#define O_HT    23552              // hT [k=128][36] (m contiguous)
#define O_SX    28160              // xT double buffer 2 x [6][36]
#define O_INT   28592              // nobs[32], samp[32]
#define SMEM_FLOATS 28656
#define SMEM_BYTES  (SMEM_FLOATS * 4)
// head overlays (all below O_SX, sSamp/sNobs preserved)
#define O_WTS   0                  // [128][132] = 16896
#define O_XCAT  16896              // [32][256] = 8192   (C1 overlays this after sync)
#define O_WC2   25088              // [9][132]  = 1188 -> 26276
#define O_C1    O_XCAT

// ---------------- helpers ----------------
__device__ __forceinline__ unsigned smem_u32(const void* p) {
    unsigned r;
    asm("{ .reg .u64 t; cvta.to.shared.u64 t, %1; cvt.u32.u64 %0, t; }" : "=r"(r) : "l"(p));
    return r;
}
__device__ __forceinline__ void cpa16(unsigned dst, const void* src) {
    asm volatile("cp.async.cg.shared.global [%0], [%1], 16;" :: "r"(dst), "l"(src));
}
__device__ __forceinline__ void cpa4(unsigned dst, const void* src) {
    asm volatile("cp.async.ca.shared.global [%0], [%1], 4;" :: "r"(dst), "l"(src));
}
#define CP_COMMIT()  asm volatile("cp.async.commit_group;" ::: "memory")
#define CP_WAIT1()   asm volatile("cp.async.wait_group 1;" ::: "memory")
#define CP_WAIT0()   asm volatile("cp.async.wait_group 0;" ::: "memory")

__device__ __forceinline__ void fma2(u64 &d, u64 a, u64 b) {
    asm("fma.rn.f32x2 %0, %1, %2, %0;" : "+l"(d) : "l"(a), "l"(b));
}
__device__ __forceinline__ u64 dup2(float a) {
    u64 r; asm("mov.b64 %0, {%1, %1};" : "=l"(r) : "f"(a)); return r;
}
__device__ __forceinline__ void unp2(u64 v, float &lo, float &hi) {
    asm("mov.b64 {%0, %1}, %2;" : "=f"(lo), "=f"(hi) : "l"(v));
}
__device__ __forceinline__ float tanhfast(float x) {
    float y; asm("tanh.approx.f32 %0, %1;" : "=f"(y) : "f"(x)); return y;
}
__device__ __forceinline__ float sigfast(float x) {
    return fmaf(tanhfast(0.5f * x), 0.5f, 0.5f);
}

// ---------------- pre-pass ----------------
__global__ void k_count(const float* __restrict__ s) {
    int m = blockIdx.x * blockDim.x + threadIdx.x;
    if (m >= B_TOT) return;
    const float* p = s + m * SDIM + OBS_OS;
    int cnt = 0;
#pragma unroll
    for (int t = 0; t < T_STEPS; ++t) {
        float v = p[t * OBS_TS];
        cnt += (v == v) ? 1 : 0;
    }
    g_nobs[m] = cnt;
    atomicAdd(&g_hist[cnt], 1);
    if (cnt == 0) {   // reference: x_TS input forced to 0 for empty sequences
        float4 z = make_float4(0.f, 0.f, 0.f, 0.f);
        float4* d = (float4*)(g_hout + m * HID);
#pragma unroll
        for (int q = 0; q < HID / 4; ++q) d[q] = z;
    }
}

__global__ void k_prefix() {
    int off = 0;
    for (int len = T_STEPS; len >= 0; --len) {
        g_cursor[len] = off;
        off += g_hist[len];
        g_hist[len] = 0;
    }
}

__global__ void k_scatter() {
    int m = blockIdx.x * blockDim.x + threadIdx.x;
    if (m >= B_TOT) return;
    int pos = atomicAdd(&g_cursor[g_nobs[m]], 1);
    g_perm[pos] = m;
}

// ---------------- fused main kernel ----------------
__global__ void __launch_bounds__(NTHREADS, 2)
k_main(const float* __restrict__ s,
       const float* __restrict__ W_os, const float* __restrict__ b_os,
       const float* __restrict__ W_ih, const float* __restrict__ W_hh,
       const float* __restrict__ b_ih, const float* __restrict__ b_hh,
       const float* __restrict__ W_ts, const float* __restrict__ b_ts,
       const float* __restrict__ W_c1, const float* __restrict__ b_c1,
       const float* __restrict__ W_c2, const float* __restrict__ b_c2,
       float* __restrict__ out)
{
    extern __shared__ float sm[];
    float* bufA  = sm + O_BUFA;
    float* bufB  = sm + O_BUFB;
    float* sWih  = sm + O_WIH;
    float* hT    = sm + O_HT;
    float* sX    = sm + O_SX;
    int*   sNobs = (int*)(sm + O_INT);
    int*   sSamp = sNobs + M_TILE;
    __shared__ int sTmaxS;

    const unsigned uBufA = smem_u32(bufA);
    const unsigned uBufB = smem_u32(bufB);
    const unsigned uSX   = smem_u32(sX);

    const int tid = threadIdx.x;
    const int jh  = tid & 127;    // hidden unit (owns gate rows jh+128g)
    const int mg  = tid >> 7;     // sample half: 16 samples mg*16..+15
    const int base = blockIdx.x * M_TILE;

    if (tid < M_TILE) {
        int idx = g_perm[base + tid];
        sSamp[tid] = idx;
        sNobs[tid] = g_nobs[idx];
    }
    __syncthreads();

    // prologue prefetch: group0 = chunk0 + xT(0); group1 = chunk1
#pragma unroll
    for (int q = 0; q < 8; ++q) {
        int lin = q * NTHREADS + tid;       // 0..2047 float4s
        int r = lin >> 2, cc = lin & 3;
        cpa16(uBufA + (unsigned)(r * 20 + cc * 4) * 4u,
              W_hh + r * HID + 0 * 16 + cc * 4);
    }
    if (tid < M_TILE * OBS_TS) {
        int m = tid / OBS_TS, i = tid - m * OBS_TS;
        cpa4(uSX + (unsigned)(i * 36 + m) * 4u,
             s + sSamp[m] * SDIM + OBS_OS + 0 * OBS_TS + i);
    }
    CP_COMMIT();
#pragma unroll
    for (int q = 0; q < 8; ++q) {
        int lin = q * NTHREADS + tid;
        int r = lin >> 2, cc = lin & 3;
        cpa16(uBufB + (unsigned)(r * 20 + cc * 4) * 4u,
              W_hh + r * HID + 1 * 16 + cc * 4);
    }
    CP_COMMIT();

    // stage W_ih (identical layout -> straight copy) + zero hT while prefetch flies
    for (int i = tid; i < 512 * OBS_TS; i += NTHREADS) sWih[i] = W_ih[i];
    for (int i = tid; i < 128 * 36; i += NTHREADS) hT[i] = 0.0f;
    if (tid == 0) {
        int tm = 0;
        for (int m = 0; m < M_TILE; ++m) tm = max(tm, sNobs[m]);
        sTmaxS = tm;
    }

    float biasv[4];
#pragma unroll
    for (int g = 0; g < 4; ++g)
        biasv[g] = b_ih[jh + 128 * g] + b_hh[jh + 128 * g];
    float creg[16];
#pragma unroll
    for (int e = 0; e < 16; ++e) creg[e] = 0.0f;

    __syncthreads();
    const int tmax = sTmaxS;

    // ================= LSTM recurrence =================
    for (int t = 0; t < tmax; ++t) {
        float* xTc = sX + (t & 1) * 216;

        u64 aI[8], aF[8], aG[8], aO[8];   // 8 m-pairs each (16 samples)
        {
            u64 bi = dup2(biasv[0]), bf = dup2(biasv[1]);
            u64 bg = dup2(biasv[2]), bo = dup2(biasv[3]);
#pragma unroll
            for (int p = 0; p < 8; ++p) { aI[p] = bi; aF[p] = bf; aG[p] = bg; aO[p] = bo; }
        }

#pragma unroll 2
        for (int c = 0; c < 8; ++c) {
            CP_WAIT1();
            __syncthreads();            // chunk c visible; prev buf readers done; hT published

            if (c == 0) {
                // sanitize xT(t): NaN -> 0 (consumed at c==1 after its barrier)
                if (tid < M_TILE * OBS_TS) {
                    int m = tid / OBS_TS, i = tid - m * OBS_TS;
                    float v = xTc[i * 36 + m];
                    xTc[i * 36 + m] = (v == v) ? v : 0.0f;
                }
            }
            if (c == 1) {
                // x contribution
#pragma unroll
                for (int i = 0; i < OBS_TS; ++i) {
                    u64 wi = dup2(sWih[(jh      ) * 6 + i]);
                    u64 wf = dup2(sWih[(jh + 128) * 6 + i]);
                    u64 wg = dup2(sWih[(jh + 256) * 6 + i]);
                    u64 wo = dup2(sWih[(jh + 384) * 6 + i]);
                    const ulonglong2* xp = (const ulonglong2*)(xTc + i * 36 + mg * 16);
                    ulonglong2 x01 = xp[0], x23 = xp[1], x45 = xp[2], x67 = xp[3];
                    fma2(aI[0], wi, x01.x); fma2(aI[1], wi, x01.y);
                    fma2(aI[2], wi, x23.x); fma2(aI[3], wi, x23.y);
                    fma2(aI[4], wi, x45.x); fma2(aI[5], wi, x45.y);
                    fma2(aI[6], wi, x67.x); fma2(aI[7], wi, x67.y);
                    fma2(aF[0], wf, x01.x); fma2(aF[1], wf, x01.y);
                    fma2(aF[2], wf, x23.x); fma2(aF[3], wf, x23.y);
                    fma2(aF[4], wf, x45.x); fma2(aF[5], wf, x45.y);
                    fma2(aF[6], wf, x67.x); fma2(aF[7], wf, x67.y);
                    fma2(aG[0], wg, x01.x); fma2(aG[1], wg, x01.y);
                    fma2(aG[2], wg, x23.x); fma2(aG[3], wg, x23.y);
                    fma2(aG[4], wg, x45.x); fma2(aG[5], wg, x45.y);
                    fma2(aG[6], wg, x67.x); fma2(aG[7], wg, x67.y);
                    fma2(aO[0], wo, x01.x); fma2(aO[1], wo, x01.y);
                    fma2(aO[2], wo, x23.x); fma2(aO[3], wo, x23.y);
                    fma2(aO[4], wo, x45.x); fma2(aO[5], wo, x45.y);
                    fma2(aO[6], wo, x67.x); fma2(aO[7], wo, x67.y);
                }
            }

            const float* buf = (c & 1) ? bufB : bufA;
#pragma unroll 1
            for (int kk = 0; kk < 4; ++kk) {
                float4 wI = *(const float4*)(buf + (jh      ) * 20 + kk * 4);
                float4 wF = *(const float4*)(buf + (jh + 128) * 20 + kk * 4);
                float4 wG = *(const float4*)(buf + (jh + 256) * 20 + kk * 4);
                float4 wO = *(const float4*)(buf + (jh + 384) * 20 + kk * 4);
                const float* hb = hT + (c * 16 + kk * 4) * 36 + mg * 16;
#pragma unroll
                for (int q = 0; q < 4; ++q) {
                    const ulonglong2* hp = (const ulonglong2*)(hb + q * 36);
                    ulonglong2 h01 = hp[0], h23 = hp[1], h45 = hp[2], h67 = hp[3];
                    float wIq = (q == 0) ? wI.x : (q == 1) ? wI.y : (q == 2) ? wI.z : wI.w;
                    float wFq = (q == 0) ? wF.x : (q == 1) ? wF.y : (q == 2) ? wF.z : wF.w;
                    float wGq = (q == 0) ? wG.x : (q == 1) ? wG.y : (q == 2) ? wG.z : wG.w;
                    float wOq = (q == 0) ? wO.x : (q == 1) ? wO.y : (q == 2) ? wO.z : wO.w;
                    u64 wi = dup2(wIq), wf = dup2(wFq), wg = dup2(wGq), wo = dup2(wOq);
                    fma2(aI[0], wi, h01.x); fma2(aI[1], wi, h01.y);
                    fma2(aI[2], wi, h23.x); fma2(aI[3], wi, h23.y);
                    fma2(aI[4], wi, h45.x); fma2(aI[5], wi, h45.y);
                    fma2(aI[6], wi, h67.x); fma2(aI[7], wi, h67.y);
                    fma2(aF[0], wf, h01.x); fma2(aF[1], wf, h01.y);
                    fma2(aF[2], wf, h23.x); fma2(aF[3], wf, h23.y);
                    fma2(aF[4], wf, h45.x); fma2(aF[5], wf, h45.y);
                    fma2(aF[6], wf, h67.x); fma2(aF[7], wf, h67.y);
                    fma2(aG[0], wg, h01.x); fma2(aG[1], wg, h01.y);
                    fma2(aG[2], wg, h23.x); fma2(aG[3], wg, h23.y);
                    fma2(aG[4], wg, h45.x); fma2(aG[5], wg, h45.y);
                    fma2(aG[6], wg, h67.x); fma2(aG[7], wg, h67.y);
                    fma2(aO[0], wo, h01.x); fma2(aO[1], wo, h01.y);
                    fma2(aO[2], wo, h23.x); fma2(aO[3], wo, h23.y);
                    fma2(aO[4], wo, h45.x); fma2(aO[5], wo, h45.y);
                    fma2(aO[6], wo, h67.x); fma2(aO[7], wo, h67.y);
                }
            }
            __syncthreads();            // all reads of this buf + hT done

            // prefetch chunk (c+2)&7 (next step's chunks when wrapping)
            int nc = (c + 2) & 7;
            unsigned ubuf = (c & 1) ? uBufB : uBufA;
#pragma unroll
            for (int q = 0; q < 8; ++q) {
                int lin = q * NTHREADS + tid;
                int r = lin >> 2, cc2 = lin & 3;
                cpa16(ubuf + (unsigned)(r * 20 + cc2 * 4) * 4u,
                      W_hh + r * HID + nc * 16 + cc2 * 4);
            }
            if (c == 6 && (t + 1) < tmax && tid < M_TILE * OBS_TS) {
                int m = tid / OBS_TS, i = tid - m * OBS_TS;
                cpa4(uSX + (unsigned)(((t + 1) & 1) * 216 + i * 36 + m) * 4u,
                     s + sSamp[m] * SDIM + OBS_OS + (t + 1) * OBS_TS + i);
            }
            CP_COMMIT();
        }

        // update: gates for (jh, 16 samples) in registers — no exchange
#pragma unroll
        for (int p = 0; p < 8; ++p) {
            float i0, i1, f0, f1, g0, g1, o0, o1;
            unp2(aI[p], i0, i1);
            unp2(aF[p], f0, f1);
            unp2(aG[p], g0, g1);
            unp2(aO[p], o0, o1);
#pragma unroll
            for (int e = 0; e < 2; ++e) {
                int sloc = p * 2 + e;
                int m = mg * 16 + sloc;
                float gi = e ? i1 : i0, gf = e ? f1 : f0;
                float gg = e ? g1 : g0, go = e ? o1 : o0;
                float iv = sigfast(gi), fv = sigfast(gf);
                float gv = tanhfast(gg), ov = sigfast(go);
                float cv = fmaf(fv, creg[sloc], iv * gv);
                creg[sloc] = cv;
                float hv = ov * tanhfast(cv);
                hT[jh * 36 + m] = hv;
                if (t == sNobs[m] - 1) g_hout[sSamp[m] * HID + jh] = hv;
            }
        }
        // next step's chunk-0 barrier publishes hT
    }

    CP_WAIT0();
    __syncthreads();

    // ================= head =================
    float* sWts  = sm + O_WTS;
    float* sXcat = sm + O_XCAT;
    float* sWc2  = sm + O_WC2;
    float* sC1o  = sm + O_C1;

    // stage W_ts [128][132]
#pragma unroll
    for (int q = 0; q < 17; ++q) {
        int idx = q * NTHREADS + tid;       // float4 index
        if (idx < 128 * 32) {
            int r = idx >> 5, cc = idx & 31;
            *(float4*)(sWts + r * 132 + cc * 4) = *(const float4*)(W_ts + r * HID + cc * 4);
        }
    }
    // stage W_c2 [9][132] — STRIDED (288 float4s > NTHREADS; this was the R7 bug)
    for (int idx = tid; idx < NACT * 32; idx += NTHREADS) {
        int o = idx >> 5, kb = (idx & 31) * 4;
        *(float4*)(sWc2 + o * 132 + kb) = *(const float4*)(W_c2 + o * HID + kb);
    }
    __syncthreads();

    // x_OS = relu(s_OS @ W_os^T + b_os) -> xcat[:, :128] (direct LDG of s_OS)
    {
        float wos[8];
#pragma unroll
        for (int i = 0; i < 8; ++i) wos[i] = W_os[jh * 8 + i];
        float bos = b_os[jh];
#pragma unroll
        for (int mm = 0; mm < 16; ++mm) {
            int m = mg * 16 + mm;
            const float4* sp = (const float4*)(s + sSamp[m] * SDIM);
            float4 s0 = sp[0], s1 = sp[1];
            float a = bos;
            a = fmaf(wos[0], s0.x, a); a = fmaf(wos[1], s0.y, a);
            a = fmaf(wos[2], s0.z, a); a = fmaf(wos[3], s0.w, a);
            a = fmaf(wos[4], s1.x, a); a = fmaf(wos[5], s1.y, a);
            a = fmaf(wos[6], s1.z, a); a = fmaf(wos[7], s1.w, a);
            sXcat[m * 256 + jh] = fmaxf(a, 0.0f);
        }
    }
    // x_TS = relu(hout @ W_ts^T + b_ts) -> xcat[:, 128:]; hout via uniform LDG
    {
        float a16[16];
#pragma unroll
        for (int mm = 0; mm < 16; ++mm) a16[mm] = 0.0f;
#pragma unroll 1
        for (int k4 = 0; k4 < 32; ++k4) {
            float4 w = *(const float4*)(sWts + jh * 132 + k4 * 4);
#pragma unroll
            for (int mm = 0; mm < 16; ++mm) {
                int m = mg * 16 + mm;
                float4 h = *(const float4*)(g_hout + sSamp[m] * HID + k4 * 4);
                float a = a16[mm];
                a = fmaf(w.x, h.x, a);
                a = fmaf(w.y, h.y, a);
                a = fmaf(w.z, h.z, a);
                a = fmaf(w.w, h.w, a);
                a16[mm] = a;
            }
        }
        float bts = b_ts[jh];
#pragma unroll
        for (int mm = 0; mm < 16; ++mm) {
            int m = mg * 16 + mm;
            sXcat[m * 256 + HID + jh] = fmaxf(a16[mm] + bts, 0.0f);
        }
    }
    __syncthreads();

    // c1 = relu(xcat @ W_c1^T + b_c1), K=256 in two staged halves
    {
        float a16[16];
#pragma unroll
        for (int mm = 0; mm < 16; ++mm) a16[mm] = 0.0f;
#pragma unroll 1
        for (int half = 0; half < 2; ++half) {
            __syncthreads();
#pragma unroll
            for (int q = 0; q < 17; ++q) {
                int idx = q * NTHREADS + tid;
                if (idx < 128 * 32) {
                    int r = idx >> 5, cc = idx & 31;
                    *(float4*)(sWts + r * 132 + cc * 4) =
                        *(const float4*)(W_c1 + r * 256 + half * 128 + cc * 4);
                }
            }
            __syncthreads();
#pragma unroll 1
            for (int k4 = 0; k4 < 32; ++k4) {
                float4 w = *(const float4*)(sWts + jh * 132 + k4 * 4);
#pragma unroll
                for (int mm = 0; mm < 16; ++mm) {
                    int m = mg * 16 + mm;
                    float4 x = *(const float4*)(sXcat + m * 256 + half * 128 + k4 * 4);
                    float a = a16[mm];
                    a = fmaf(w.x, x.x, a);
                    a = fmaf(w.y, x.y, a);
                    a = fmaf(w.z, x.z, a);
                    a = fmaf(w.w, x.w, a);
                    a16[mm] = a;
                }
            }
        }
        __syncthreads();   // xcat reads done before C1 overlays it
        float bc1 = b_c1[jh];
#pragma unroll
        for (int mm = 0; mm < 16; ++mm) {
            int m = mg * 16 + mm;
            sC1o[m * 132 + jh] = fmaxf(a16[mm] + bc1, 0.0f);
        }
    }
    __syncthreads();

    // out = c1 @ W_c2^T + b_c2 (288 outputs)
    for (int idx = tid; idx < M_TILE * NACT; idx += NTHREADS) {
        int m = idx / NACT, o = idx - m * NACT;
        float a = b_c2[o];
#pragma unroll 1
        for (int k4 = 0; k4 < 32; ++k4) {
            float4 w = *(const float4*)(sWc2 + o * 132 + k4 * 4);
            float4 x = *(const float4*)(sC1o + m * 132 + k4 * 4);
            a = fmaf(w.x, x.x, a);
            a = fmaf(w.y, x.y, a);
            a = fmaf(w.z, x.z, a);
            a = fmaf(w.w, x.w, a);
        }
        out[sSamp[m] * NACT + o] = a;
    }
}

// ---------------- launch ----------------
extern "C" void kernel_launch(void* const* d_in, const int* in_sizes, int n_in,
                              void* d_out, int out_size) {
    const float* s    = (const float*)d_in[0];
    const float* W_os = (const float*)d_in[1];
    const float* b_os = (const float*)d_in[2];
    const float* W_ih = (const float*)d_in[3];
    const float* W_hh = (const float*)d_in[4];
    const float* b_ih = (const float*)d_in[5];
    const float* b_hh = (const float*)d_in[6];
    const float* W_ts = (const float*)d_in[7];
    const float* b_ts = (const float*)d_in[8];
    const float* W_c1 = (const float*)d_in[9];
    const float* b_c1 = (const float*)d_in[10];
    const float* W_c2 = (const float*)d_in[11];
    const float* b_c2 = (const float*)d_in[12];
    float* out = (float*)d_out;

    cudaFuncSetAttribute(k_main, cudaFuncAttributeMaxDynamicSharedMemorySize, SMEM_BYTES);

    k_count<<<B_TOT / 256, 256>>>(s);
    k_prefix<<<1, 1>>>();
    k_scatter<<<B_TOT / 256, 256>>>();
    k_main<<<NCTA, NTHREADS, SMEM_BYTES>>>(s, W_os, b_os, W_ih, W_hh, b_ih, b_hh,
                                           W_ts, b_ts, W_c1, b_c1, W_c2, b_c2, out);
}

// round 13
// speedup vs baseline: 1.0304x; 1.0275x over previous
#include <cuda_runtime.h>
#include <math.h>
#include <cstdint>

#define B_TOT   32768
#define T_STEPS 32
#define HID     128
#define OBS_OS  8
#define OBS_TS  6
#define SDIM    200
#define NACT    9
#define M_TILE  32
#define NTHREADS 256
#define NCTA    (B_TOT / M_TILE)

typedef unsigned long long u64;

// ---------------- scratch ----------------
__device__ int   g_nobs[B_TOT];
__device__ int   g_perm[B_TOT];
__device__ int   g_hist[T_STEPS + 1];
__device__ int   g_cursor[T_STEPS + 1];
__device__ float g_hout[B_TOT * HID];     // h snapshot (16 MB static scratch)

// ---------------- shared layout (float offsets), total 28656 fl = 111.9 KB ----------------
#define O_BUFA  0                  // W chunk buf A [512][20] (16 K + pad)
#define O_BUFB  10240              // W chunk buf B [512][20]
#define O_WIH   20480              // W_ih [512][6] packed
#define O_HT    23552              // hT [k=128][36] (m contiguous)
#define O_SX    28160              // xT double buffer 2 x [6][36]
#define O_INT   28592              // nobs[32], samp[32]
#define SMEM_FLOATS 28656
#define SMEM_BYTES  (SMEM_FLOATS * 4)
// head overlays
#define O_WTS   0                  // [128][132] = 16896
#define O_XCAT  16896              // [32][256] = 8192
#define O_WC2   25088              // [9][132]  = 1188
#define O_C1    O_XCAT

// ---------------- helpers ----------------
__device__ __forceinline__ unsigned smem_u32(const void* p) {
    unsigned r;
    asm("{ .reg .u64 t; cvta.to.shared.u64 t, %1; cvt.u32.u64 %0, t; }" : "=r"(r) : "l"(p));
    return r;
}
__device__ __forceinline__ void cpa16(unsigned dst, const void* src) {
    asm volatile("cp.async.cg.shared.global [%0], [%1], 16;" :: "r"(dst), "l"(src));
}
__device__ __forceinline__ void cpa4(unsigned dst, const void* src) {
    asm volatile("cp.async.ca.shared.global [%0], [%1], 4;" :: "r"(dst), "l"(src));
}
#define CP_COMMIT()  asm volatile("cp.async.commit_group;" ::: "memory")
#define CP_WAIT0()   asm volatile("cp.async.wait_group 0;" ::: "memory")

__device__ __forceinline__ void fma2(u64 &d, u64 a, u64 b) {
    asm("fma.rn.f32x2 %0, %1, %2, %0;" : "+l"(d) : "l"(a), "l"(b));
}
__device__ __forceinline__ u64 dup2(float a) {
    u64 r; asm("mov.b64 %0, {%1, %1};" : "=l"(r) : "f"(a)); return r;
}
__device__ __forceinline__ void unp2(u64 v, float &lo, float &hi) {
    asm("mov.b64 {%0, %1}, %2;" : "=f"(lo), "=f"(hi) : "l"(v));
}
__device__ __forceinline__ float tanhfast(float x) {
    float y; asm("tanh.approx.f32 %0, %1;" : "=f"(y) : "f"(x)); return y;
}
__device__ __forceinline__ float sigfast(float x) {
    return fmaf(tanhfast(0.5f * x), 0.5f, 0.5f);
}

// ---------------- pre-pass ----------------
__global__ void k_count(const float* __restrict__ s) {
    int m = blockIdx.x * blockDim.x + threadIdx.x;
    if (m >= B_TOT) return;
    const float* p = s + m * SDIM + OBS_OS;
    int cnt = 0;
#pragma unroll
    for (int t = 0; t < T_STEPS; ++t) {
        float v = p[t * OBS_TS];
        cnt += (v == v) ? 1 : 0;
    }
    g_nobs[m] = cnt;
    atomicAdd(&g_hist[cnt], 1);
    if (cnt == 0) {   // reference: x_TS input forced to 0 for empty sequences
        float4 z = make_float4(0.f, 0.f, 0.f, 0.f);
        float4* d = (float4*)(g_hout + m * HID);
#pragma unroll
        for (int q = 0; q < HID / 4; ++q) d[q] = z;
    }
}

__global__ void k_prefix() {
    int off = 0;
    for (int len = T_STEPS; len >= 0; --len) {
        g_cursor[len] = off;
        off += g_hist[len];
        g_hist[len] = 0;
    }
}

__global__ void k_scatter() {
    int m = blockIdx.x * blockDim.x + threadIdx.x;
    if (m >= B_TOT) return;
    int pos = atomicAdd(&g_cursor[g_nobs[m]], 1);
    g_perm[pos] = m;
}

// ---------------- fused main kernel ----------------
__global__ void __launch_bounds__(NTHREADS, 2)
k_main(const float* __restrict__ s,
       const float* __restrict__ W_os, const float* __restrict__ b_os,
       const float* __restrict__ W_ih, const float* __restrict__ W_hh,
       const float* __restrict__ b_ih, const float* __restrict__ b_hh,
       const float* __restrict__ W_ts, const float* __restrict__ b_ts,
       const float* __restrict__ W_c1, const float* __restrict__ b_c1,
       const float* __restrict__ W_c2, const float* __restrict__ b_c2,
       float* __restrict__ out)
{
    extern __shared__ float sm[];
    float* bufA  = sm + O_BUFA;
    float* bufB  = sm + O_BUFB;
    float* sWih  = sm + O_WIH;
    float* hT    = sm + O_HT;
    float* sX    = sm + O_SX;
    int*   sNobs = (int*)(sm + O_INT);
    int*   sSamp = sNobs + M_TILE;
    __shared__ int sTmaxS;

    const unsigned uBufA = smem_u32(bufA);
    const unsigned uBufB = smem_u32(bufB);
    const unsigned uSX   = smem_u32(sX);

    const int tid = threadIdx.x;
    const int jh  = tid & 127;    // hidden unit (owns gate rows jh+128g)
    const int mg  = tid >> 7;     // sample half: 16 samples mg*16..+15
    const int base = blockIdx.x * M_TILE;

    if (tid < M_TILE) {
        int idx = g_perm[base + tid];
        sSamp[tid] = idx;
        sNobs[tid] = g_nobs[idx];
    }
    __syncthreads();

    // prologue: ONE group = chunk0 + xT(0)
#pragma unroll
    for (int q = 0; q < 8; ++q) {
        int lin = q * NTHREADS + tid;       // 0..2047 float4s
        int r = lin >> 2, cc = lin & 3;
        cpa16(uBufA + (unsigned)(r * 20 + cc * 4) * 4u,
              W_hh + r * HID + 0 * 16 + cc * 4);
    }
    if (tid < M_TILE * OBS_TS) {
        int m = tid / OBS_TS, i = tid - m * OBS_TS;
        cpa4(uSX + (unsigned)(i * 36 + m) * 4u,
             s + sSamp[m] * SDIM + OBS_OS + 0 * OBS_TS + i);
    }
    CP_COMMIT();

    // stage W_ih + zero hT while prefetch flies
    for (int i = tid; i < 512 * OBS_TS; i += NTHREADS) sWih[i] = W_ih[i];
    for (int i = tid; i < 128 * 36; i += NTHREADS) hT[i] = 0.0f;
    if (tid == 0) {
        int tm = 0;
        for (int m = 0; m < M_TILE; ++m) tm = max(tm, sNobs[m]);
        sTmaxS = tm;
    }

    float biasv[4];
#pragma unroll
    for (int g = 0; g < 4; ++g)
        biasv[g] = b_ih[jh + 128 * g] + b_hh[jh + 128 * g];
    float creg[16];
#pragma unroll
    for (int e = 0; e < 16; ++e) creg[e] = 0.0f;

    __syncthreads();
    const int tmax = sTmaxS;

    // ================= LSTM recurrence =================
    for (int t = 0; t < tmax; ++t) {
        float* xTc = sX + (t & 1) * 216;

        u64 aI[8], aF[8], aG[8], aO[8];   // 8 m-pairs each (16 samples)
        {
            u64 bi = dup2(biasv[0]), bf = dup2(biasv[1]);
            u64 bg = dup2(biasv[2]), bo = dup2(biasv[3]);
#pragma unroll
            for (int p = 0; p < 8; ++p) { aI[p] = bi; aF[p] = bf; aG[p] = bg; aO[p] = bo; }
        }

#pragma unroll 2
        for (int c = 0; c < 8; ++c) {
            // single barrier per chunk:
            //  - CP_WAIT0 makes this thread's chunk-c copies complete
            //  - barrier publishes all threads' copies AND proves chunk-(c-1)
            //    readers are done, so buf[(c+1)&1] (which held c-1) is reusable
            CP_WAIT0();
            __syncthreads();

            // prefetch chunk c+1 into the parity buffer (distance-1)
            {
                int nc = (c + 1) & 7;
                unsigned ubuf = ((c + 1) & 1) ? uBufB : uBufA;
#pragma unroll
                for (int q = 0; q < 8; ++q) {
                    int lin = q * NTHREADS + tid;
                    int r = lin >> 2, cc2 = lin & 3;
                    cpa16(ubuf + (unsigned)(r * 20 + cc2 * 4) * 4u,
                          W_hh + r * HID + nc * 16 + cc2 * 4);
                }
                if (c == 7 && (t + 1) < tmax && tid < M_TILE * OBS_TS) {
                    int m = tid / OBS_TS, i = tid - m * OBS_TS;
                    cpa4(uSX + (unsigned)(((t + 1) & 1) * 216 + i * 36 + m) * 4u,
                         s + sSamp[m] * SDIM + OBS_OS + (t + 1) * OBS_TS + i);
                }
                CP_COMMIT();
            }

            if (c == 0) {
                // sanitize xT(t): NaN -> 0 (published by c==1's top barrier)
                if (tid < M_TILE * OBS_TS) {
                    int m = tid / OBS_TS, i = tid - m * OBS_TS;
                    float v = xTc[i * 36 + m];
                    xTc[i * 36 + m] = (v == v) ? v : 0.0f;
                }
            }
            if (c == 1) {
                // x contribution
#pragma unroll
                for (int i = 0; i < OBS_TS; ++i) {
                    u64 wi = dup2(sWih[(jh      ) * 6 + i]);
                    u64 wf = dup2(sWih[(jh + 128) * 6 + i]);
                    u64 wg = dup2(sWih[(jh + 256) * 6 + i]);
                    u64 wo = dup2(sWih[(jh + 384) * 6 + i]);
                    const ulonglong2* xp = (const ulonglong2*)(xTc + i * 36 + mg * 16);
                    ulonglong2 x01 = xp[0], x23 = xp[1], x45 = xp[2], x67 = xp[3];
                    fma2(aI[0], wi, x01.x); fma2(aI[1], wi, x01.y);
                    fma2(aI[2], wi, x23.x); fma2(aI[3], wi, x23.y);
                    fma2(aI[4], wi, x45.x); fma2(aI[5], wi, x45.y);
                    fma2(aI[6], wi, x67.x); fma2(aI[7], wi, x67.y);
                    fma2(aF[0], wf, x01.x); fma2(aF[1], wf, x01.y);
                    fma2(aF[2], wf, x23.x); fma2(aF[3], wf, x23.y);
                    fma2(aF[4], wf, x45.x); fma2(aF[5], wf, x45.y);
                    fma2(aF[6], wf, x67.x); fma2(aF[7], wf, x67.y);
                    fma2(aG[0], wg, x01.x); fma2(aG[1], wg, x01.y);
                    fma2(aG[2], wg, x23.x); fma2(aG[3], wg, x23.y);
                    fma2(aG[4], wg, x45.x); fma2(aG[5], wg, x45.y);
                    fma2(aG[6], wg, x67.x); fma2(aG[7], wg, x67.y);
                    fma2(aO[0], wo, x01.x); fma2(aO[1], wo, x01.y);
                    fma2(aO[2], wo, x23.x); fma2(aO[3], wo, x23.y);
                    fma2(aO[4], wo, x45.x); fma2(aO[5], wo, x45.y);
                    fma2(aO[6], wo, x67.x); fma2(aO[7], wo, x67.y);
                }
            }

            const float* buf = (c & 1) ? bufB : bufA;
#pragma unroll 1
            for (int kk = 0; kk < 4; ++kk) {
                float4 wI = *(const float4*)(buf + (jh      ) * 20 + kk * 4);
                float4 wF = *(const float4*)(buf + (jh + 128) * 20 + kk * 4);
                float4 wG = *(const float4*)(buf + (jh + 256) * 20 + kk * 4);
                float4 wO = *(const float4*)(buf + (jh + 384) * 20 + kk * 4);
                const float* hb = hT + (c * 16 + kk * 4) * 36 + mg * 16;
#pragma unroll
                for (int q = 0; q < 4; ++q) {
                    const ulonglong2* hp = (const ulonglong2*)(hb + q * 36);
                    ulonglong2 h01 = hp[0], h23 = hp[1], h45 = hp[2], h67 = hp[3];
                    float wIq = (q == 0) ? wI.x : (q == 1) ? wI.y : (q == 2) ? wI.z : wI.w;
                    float wFq = (q == 0) ? wF.x : (q == 1) ? wF.y : (q == 2) ? wF.z : wF.w;
                    float wGq = (q == 0) ? wG.x : (q == 1) ? wG.y : (q == 2) ? wG.z : wG.w;
                    float wOq = (q == 0) ? wO.x : (q == 1) ? wO.y : (q == 2) ? wO.z : wO.w;
                    u64 wi = dup2(wIq), wf = dup2(wFq), wg = dup2(wGq), wo = dup2(wOq);
                    fma2(aI[0], wi, h01.x); fma2(aI[1], wi, h01.y);
                    fma2(aI[2], wi, h23.x); fma2(aI[3], wi, h23.y);
                    fma2(aI[4], wi, h45.x); fma2(aI[5], wi, h45.y);
                    fma2(aI[6], wi, h67.x); fma2(aI[7], wi, h67.y);
                    fma2(aF[0], wf, h01.x); fma2(aF[1], wf, h01.y);
                    fma2(aF[2], wf, h23.x); fma2(aF[3], wf, h23.y);
                    fma2(aF[4], wf, h45.x); fma2(aF[5], wf, h45.y);
                    fma2(aF[6], wf, h67.x); fma2(aF[7], wf, h67.y);
                    fma2(aG[0], wg, h01.x); fma2(aG[1], wg, h01.y);
                    fma2(aG[2], wg, h23.x); fma2(aG[3], wg, h23.y);
                    fma2(aG[4], wg, h45.x); fma2(aG[5], wg, h45.y);
                    fma2(aG[6], wg, h67.x); fma2(aG[7], wg, h67.y);
                    fma2(aO[0], wo, h01.x); fma2(aO[1], wo, h01.y);
                    fma2(aO[2], wo, h23.x); fma2(aO[3], wo, h23.y);
                    fma2(aO[4], wo, h45.x); fma2(aO[5], wo, h45.y);
                    fma2(aO[6], wo, h67.x); fma2(aO[7], wo, h67.y);
                }
            }
            // NO trailing barrier — next chunk's top barrier covers buffer reuse
        }

        __syncthreads();   // all hT(t-1) readers done before update writes hT(t)

        // update: gates for (jh, 16 samples) in registers — no exchange
#pragma unroll
        for (int p = 0; p < 8; ++p) {
            float i0, i1, f0, f1, g0, g1, o0, o1;
            unp2(aI[p], i0, i1);
            unp2(aF[p], f0, f1);
            unp2(aG[p], g0, g1);
            unp2(aO[p], o0, o1);
#pragma unroll
            for (int e = 0; e < 2; ++e) {
                int sloc = p * 2 + e;
                int m = mg * 16 + sloc;
                float gi = e ? i1 : i0, gf = e ? f1 : f0;
                float gg = e ? g1 : g0, go = e ? o1 : o0;
                float iv = sigfast(gi), fv = sigfast(gf);
                float gv = tanhfast(gg), ov = sigfast(go);
                float cv = fmaf(fv, creg[sloc], iv * gv);
                creg[sloc] = cv;
                float hv = ov * tanhfast(cv);
                hT[jh * 36 + m] = hv;
                if (t == sNobs[m] - 1) g_hout[sSamp[m] * HID + jh] = hv;
            }
        }
        // next step's chunk-0 top barrier publishes hT(t)
    }

    CP_WAIT0();
    __syncthreads();

    // ================= head =================
    float* sWts  = sm + O_WTS;
    float* sXcat = sm + O_XCAT;
    float* sWc2  = sm + O_WC2;
    float* sC1o  = sm + O_C1;

    // stage W_ts [128][132]
#pragma unroll
    for (int q = 0; q < 17; ++q) {
        int idx = q * NTHREADS + tid;       // float4 index
        if (idx < 128 * 32) {
            int r = idx >> 5, cc = idx & 31;
            *(float4*)(sWts + r * 132 + cc * 4) = *(const float4*)(W_ts + r * HID + cc * 4);
        }
    }
    // stage W_c2 [9][132] — strided (288 float4s > NTHREADS)
    for (int idx = tid; idx < NACT * 32; idx += NTHREADS) {
        int o = idx >> 5, kb = (idx & 31) * 4;
        *(float4*)(sWc2 + o * 132 + kb) = *(const float4*)(W_c2 + o * HID + kb);
    }
    __syncthreads();

    // x_OS = relu(s_OS @ W_os^T + b_os) -> xcat[:, :128] (direct LDG of s_OS)
    {
        float wos[8];
#pragma unroll
        for (int i = 0; i < 8; ++i) wos[i] = W_os[jh * 8 + i];
        float bos = b_os[jh];
#pragma unroll
        for (int mm = 0; mm < 16; ++mm) {
            int m = mg * 16 + mm;
            const float4* sp = (const float4*)(s + sSamp[m] * SDIM);
            float4 s0 = sp[0], s1 = sp[1];
            float a = bos;
            a = fmaf(wos[0], s0.x, a); a = fmaf(wos[1], s0.y, a);
            a = fmaf(wos[2], s0.z, a); a = fmaf(wos[3], s0.w, a);
            a = fmaf(wos[4], s1.x, a); a = fmaf(wos[5], s1.y, a);
            a = fmaf(wos[6], s1.z, a); a = fmaf(wos[7], s1.w, a);
            sXcat[m * 256 + jh] = fmaxf(a, 0.0f);
        }
    }
    // x_TS = relu(hout @ W_ts^T + b_ts) -> xcat[:, 128:]; hout via uniform LDG
    {
        float a16[16];
#pragma unroll
        for (int mm = 0; mm < 16; ++mm) a16[mm] = 0.0f;
#pragma unroll 1
        for (int k4 = 0; k4 < 32; ++k4) {
            float4 w = *(const float4*)(sWts + jh * 132 + k4 * 4);
#pragma unroll
            for (int mm = 0; mm < 16; ++mm) {
                int m = mg * 16 + mm;
                float4 h = *(const float4*)(g_hout + sSamp[m] * HID + k4 * 4);
                float a = a16[mm];
                a = fmaf(w.x, h.x, a);
                a = fmaf(w.y, h.y, a);
                a = fmaf(w.z, h.z, a);
                a = fmaf(w.w, h.w, a);
                a16[mm] = a;
            }
        }
        float bts = b_ts[jh];
#pragma unroll
        for (int mm = 0; mm < 16; ++mm) {
            int m = mg * 16 + mm;
            sXcat[m * 256 + HID + jh] = fmaxf(a16[mm] + bts, 0.0f);
        }
    }
    __syncthreads();

    // c1 = relu(xcat @ W_c1^T + b_c1), K=256 in two staged halves
    {
        float a16[16];
#pragma unroll
        for (int mm = 0; mm < 16; ++mm) a16[mm] = 0.0f;
#pragma unroll 1
        for (int half = 0; half < 2; ++half) {
            __syncthreads();
#pragma unroll
            for (int q = 0; q < 17; ++q) {
                int idx = q * NTHREADS + tid;
                if (idx < 128 * 32) {
                    int r = idx >> 5, cc = idx & 31;
                    *(float4*)(sWts + r * 132 + cc * 4) =
                        *(const float4*)(W_c1 + r * 256 + half * 128 + cc * 4);
                }
            }
            __syncthreads();
#pragma unroll 1
            for (int k4 = 0; k4 < 32; ++k4) {
                float4 w = *(const float4*)(sWts + jh * 132 + k4 * 4);
#pragma unroll
                for (int mm = 0; mm < 16; ++mm) {
                    int m = mg * 16 + mm;
                    float4 x = *(const float4*)(sXcat + m * 256 + half * 128 + k4 * 4);
                    float a = a16[mm];
                    a = fmaf(w.x, x.x, a);
                    a = fmaf(w.y, x.y, a);
                    a = fmaf(w.z, x.z, a);
                    a = fmaf(w.w, x.w, a);
                    a16[mm] = a;
                }
            }
        }
        __syncthreads();   // xcat reads done before C1 overlays it
        float bc1 = b_c1[jh];
#pragma unroll
        for (int mm = 0; mm < 16; ++mm) {
            int m = mg * 16 + mm;
            sC1o[m * 132 + jh] = fmaxf(a16[mm] + bc1, 0.0f);
        }
    }
    __syncthreads();

    // out = c1 @ W_c2^T + b_c2 (288 outputs)
    for (int idx = tid; idx < M_TILE * NACT; idx += NTHREADS) {
        int m = idx / NACT, o = idx - m * NACT;
        float a = b_c2[o];
#pragma unroll 1
        for (int k4 = 0; k4 < 32; ++k4) {
            float4 w = *(const float4*)(sWc2 + o * 132 + k4 * 4);
            float4 x = *(const float4*)(sC1o + m * 132 + k4 * 4);
            a = fmaf(w.x, x.x, a);
            a = fmaf(w.y, x.y, a);
            a = fmaf(w.z, x.z, a);
            a = fmaf(w.w, x.w, a);
        }
        out[sSamp[m] * NACT + o] = a;
    }
}

// ---------------- launch ----------------
extern "C" void kernel_launch(void* const* d_in, const int* in_sizes, int n_in,
                              void* d_out, int out_size) {
    const float* s    = (const float*)d_in[0];
    const float* W_os = (const float*)d_in[1];
    const float* b_os = (const float*)d_in[2];
    const float* W_ih = (const float*)d_in[3];
    const float* W_hh = (const float*)d_in[4];
    const float* b_ih = (const float*)d_in[5];
    const float* b_hh = (const float*)d_in[6];
    const float* W_ts = (const float*)d_in[7];
    const float* b_ts = (const float*)d_in[8];
    const float* W_c1 = (const float*)d_in[9];
    const float* b_c1 = (const float*)d_in[10];
    const float* W_c2 = (const float*)d_in[11];
    const float* b_c2 = (const float*)d_in[12];
    float* out = (float*)d_out;

    cudaFuncSetAttribute(k_main, cudaFuncAttributeMaxDynamicSharedMemorySize, SMEM_BYTES);

    k_count<<<B_TOT / 256, 256>>>(s);
    k_prefix<<<1, 1>>>();
    k_scatter<<<B_TOT / 256, 256>>>();
    k_main<<<NCTA, NTHREADS, SMEM_BYTES>>>(s, W_os, b_os, W_ih, W_hh, b_ih, b_hh,
                                           W_ts, b_ts, W_c1, b_c1, W_c2, b_c2, out);
}

// round 14
// speedup vs baseline: 1.0536x; 1.0225x over previous
#include <cuda_runtime.h>
#include <math.h>
#include <cstdint>

#define B_TOT   32768
#define T_STEPS 32
#define HID     128
#define OBS_OS  8
#define OBS_TS  6
#define SDIM    200
#define NACT    9
#define M_TILE  32
#define NTHREADS 256
#define NTILES  (B_TOT / M_TILE)
#define NPERSIST 296               // 148 SMs x 2 CTAs

typedef unsigned long long u64;

// ---------------- scratch ----------------
__device__ int   g_nobs[B_TOT];
__device__ int   g_perm[B_TOT];
__device__ int   g_hist[T_STEPS + 1];
__device__ int   g_cursor[T_STEPS + 1];
__device__ int   g_tile;
__device__ float g_hout[B_TOT * HID];     // h snapshot (16 MB static scratch)

// ---------------- shared layout (float offsets), total 28656 fl = 111.9 KB ----------------
#define O_BUFA  0                  // W chunk buf A [512][20]
#define O_BUFB  10240              // W chunk buf B [512][20]
#define O_WIH   20480              // W_ih [512][6]
#define O_HT    23552              // hT [k=128][36]
#define O_SX    28160              // xT double buffer 2 x [6][36]
#define O_INT   28592              // nobs[32], samp[32]
#define SMEM_FLOATS 28656
#define SMEM_BYTES  (SMEM_FLOATS * 4)
// head overlays (sSamp/sNobs/sX preserved)
#define O_WTS   0                  // [128][132] = 16896
#define O_XCAT  16896              // [32][256] = 8192
#define O_WC2   25088              // [9][132]  = 1188
#define O_C1    O_XCAT

// ---------------- helpers ----------------
__device__ __forceinline__ unsigned smem_u32(const void* p) {
    unsigned r;
    asm("{ .reg .u64 t; cvta.to.shared.u64 t, %1; cvt.u32.u64 %0, t; }" : "=r"(r) : "l"(p));
    return r;
}
__device__ __forceinline__ void cpa16(unsigned dst, const void* src) {
    asm volatile("cp.async.cg.shared.global [%0], [%1], 16;" :: "r"(dst), "l"(src));
}
__device__ __forceinline__ void cpa4(unsigned dst, const void* src) {
    asm volatile("cp.async.ca.shared.global [%0], [%1], 4;" :: "r"(dst), "l"(src));
}
#define CP_COMMIT()  asm volatile("cp.async.commit_group;" ::: "memory")
#define CP_WAIT0()   asm volatile("cp.async.wait_group 0;" ::: "memory")

__device__ __forceinline__ void fma2(u64 &d, u64 a, u64 b) {
    asm("fma.rn.f32x2 %0, %1, %2, %0;" : "+l"(d) : "l"(a), "l"(b));
}
__device__ __forceinline__ u64 dup2(float a) {
    u64 r; asm("mov.b64 %0, {%1, %1};" : "=l"(r) : "f"(a)); return r;
}
__device__ __forceinline__ void unp2(u64 v, float &lo, float &hi) {
    asm("mov.b64 {%0, %1}, %2;" : "=f"(lo), "=f"(hi) : "l"(v));
}
__device__ __forceinline__ float tanhfast(float x) {
    float y; asm("tanh.approx.f32 %0, %1;" : "=f"(y) : "f"(x)); return y;
}
__device__ __forceinline__ float sigfast(float x) {
    return fmaf(tanhfast(0.5f * x), 0.5f, 0.5f);
}

// ---------------- pre-pass ----------------
__global__ void k_count(const float* __restrict__ s) {
    int m = blockIdx.x * blockDim.x + threadIdx.x;
    if (m >= B_TOT) return;
    const float* p = s + m * SDIM + OBS_OS;
    int cnt = 0;
#pragma unroll
    for (int t = 0; t < T_STEPS; ++t) {
        float v = p[t * OBS_TS];
        cnt += (v == v) ? 1 : 0;
    }
    g_nobs[m] = cnt;
    atomicAdd(&g_hist[cnt], 1);
    if (cnt == 0) {   // reference: x_TS forced to 0 for empty sequences
        float4 z = make_float4(0.f, 0.f, 0.f, 0.f);
        float4* d = (float4*)(g_hout + m * HID);
#pragma unroll
        for (int q = 0; q < HID / 4; ++q) d[q] = z;
    }
}

__global__ void k_prefix() {
    int off = 0;
    for (int len = T_STEPS; len >= 0; --len) {
        g_cursor[len] = off;
        off += g_hist[len];
        g_hist[len] = 0;
    }
    g_tile = 0;            // reset persistent-tile counter each replay
}

__global__ void k_scatter() {
    int m = blockIdx.x * blockDim.x + threadIdx.x;
    if (m >= B_TOT) return;
    int pos = atomicAdd(&g_cursor[g_nobs[m]], 1);
    g_perm[pos] = m;
}

// ---------------- fused persistent main kernel ----------------
__global__ void __launch_bounds__(NTHREADS, 2)
k_main(const float* __restrict__ s,
       const float* __restrict__ W_os, const float* __restrict__ b_os,
       const float* __restrict__ W_ih, const float* __restrict__ W_hh,
       const float* __restrict__ b_ih, const float* __restrict__ b_hh,
       const float* __restrict__ W_ts, const float* __restrict__ b_ts,
       const float* __restrict__ W_c1, const float* __restrict__ b_c1,
       const float* __restrict__ W_c2, const float* __restrict__ b_c2,
       float* __restrict__ out)
{
    extern __shared__ float sm[];
    float* bufA  = sm + O_BUFA;
    float* bufB  = sm + O_BUFB;
    float* sWih  = sm + O_WIH;
    float* hT    = sm + O_HT;
    float* sX    = sm + O_SX;
    int*   sNobs = (int*)(sm + O_INT);
    int*   sSamp = sNobs + M_TILE;
    __shared__ int sTmaxS;
    __shared__ int sTile;

    const unsigned uBufA = smem_u32(bufA);
    const unsigned uBufB = smem_u32(bufB);
    const unsigned uSX   = smem_u32(sX);

    const int tid = threadIdx.x;
    const int jh  = tid & 127;
    const int mg  = tid >> 7;

    // hoisted per-thread constants (valid for every tile)
    float biasv[4];
#pragma unroll
    for (int g = 0; g < 4; ++g)
        biasv[g] = b_ih[jh + 128 * g] + b_hh[jh + 128 * g];

    for (;;) {
        if (tid == 0) sTile = atomicAdd(&g_tile, 1);
        __syncthreads();                 // publish sTile; prior tile smem reads done
        const int tile = sTile;
        if (tile >= NTILES) break;
        const int base = tile * M_TILE;

        if (tid < M_TILE) {
            int idx = g_perm[base + tid];
            sSamp[tid] = idx;
            sNobs[tid] = g_nobs[idx];
        }
        __syncthreads();                 // publish sSamp

        // prologue: chunk0 + xT(0)
#pragma unroll
        for (int q = 0; q < 8; ++q) {
            int lin = q * NTHREADS + tid;
            int r = lin >> 2, cc = lin & 3;
            cpa16(uBufA + (unsigned)(r * 20 + cc * 4) * 4u,
                  W_hh + r * HID + 0 * 16 + cc * 4);
        }
        if (tid < M_TILE * OBS_TS) {
            int m = tid / OBS_TS, i = tid - m * OBS_TS;
            cpa4(uSX + (unsigned)(i * 36 + m) * 4u,
                 s + sSamp[m] * SDIM + OBS_OS + 0 * OBS_TS + i);
        }
        CP_COMMIT();

        // stage W_ih + zero hT while prefetch flies
        for (int i = tid; i < 512 * OBS_TS; i += NTHREADS) sWih[i] = W_ih[i];
        for (int i = tid; i < 128 * 36; i += NTHREADS) hT[i] = 0.0f;
        if (tid == 0) {
            int tm = 0;
            for (int m = 0; m < M_TILE; ++m) tm = max(tm, sNobs[m]);
            sTmaxS = tm;
        }
        float creg[16];
#pragma unroll
        for (int e = 0; e < 16; ++e) creg[e] = 0.0f;

        __syncthreads();
        const int tmax = sTmaxS;

        // ================= LSTM recurrence =================
        for (int t = 0; t < tmax; ++t) {
            float* xTc = sX + (t & 1) * 216;

            u64 aI[8], aF[8], aG[8], aO[8];
            {
                u64 bi = dup2(biasv[0]), bf = dup2(biasv[1]);
                u64 bg = dup2(biasv[2]), bo = dup2(biasv[3]);
#pragma unroll
                for (int p = 0; p < 8; ++p) { aI[p] = bi; aF[p] = bf; aG[p] = bg; aO[p] = bo; }
            }

#pragma unroll 2
            for (int c = 0; c < 8; ++c) {
                CP_WAIT0();
                __syncthreads();      // chunk c visible; buf[(c+1)&1] reusable

                // distance-1 prefetch of chunk c+1
                {
                    int nc = (c + 1) & 7;
                    unsigned ubuf = ((c + 1) & 1) ? uBufB : uBufA;
#pragma unroll
                    for (int q = 0; q < 8; ++q) {
                        int lin = q * NTHREADS + tid;
                        int r = lin >> 2, cc2 = lin & 3;
                        cpa16(ubuf + (unsigned)(r * 20 + cc2 * 4) * 4u,
                              W_hh + r * HID + nc * 16 + cc2 * 4);
                    }
                    if (c == 7 && (t + 1) < tmax && tid < M_TILE * OBS_TS) {
                        int m = tid / OBS_TS, i = tid - m * OBS_TS;
                        cpa4(uSX + (unsigned)(((t + 1) & 1) * 216 + i * 36 + m) * 4u,
                             s + sSamp[m] * SDIM + OBS_OS + (t + 1) * OBS_TS + i);
                    }
                    CP_COMMIT();
                }

                if (c == 0) {
                    // sanitize xT(t): NaN -> 0 (published by c==1's top barrier)
                    if (tid < M_TILE * OBS_TS) {
                        int m = tid / OBS_TS, i = tid - m * OBS_TS;
                        float v = xTc[i * 36 + m];
                        xTc[i * 36 + m] = (v == v) ? v : 0.0f;
                    }
                }
                if (c == 1) {
                    // x contribution
#pragma unroll
                    for (int i = 0; i < OBS_TS; ++i) {
                        u64 wi = dup2(sWih[(jh      ) * 6 + i]);
                        u64 wf = dup2(sWih[(jh + 128) * 6 + i]);
                        u64 wg = dup2(sWih[(jh + 256) * 6 + i]);
                        u64 wo = dup2(sWih[(jh + 384) * 6 + i]);
                        const ulonglong2* xp = (const ulonglong2*)(xTc + i * 36 + mg * 16);
                        ulonglong2 x01 = xp[0], x23 = xp[1], x45 = xp[2], x67 = xp[3];
                        fma2(aI[0], wi, x01.x); fma2(aI[1], wi, x01.y);
                        fma2(aI[2], wi, x23.x); fma2(aI[3], wi, x23.y);
                        fma2(aI[4], wi, x45.x); fma2(aI[5], wi, x45.y);
                        fma2(aI[6], wi, x67.x); fma2(aI[7], wi, x67.y);
                        fma2(aF[0], wf, x01.x); fma2(aF[1], wf, x01.y);
                        fma2(aF[2], wf, x23.x); fma2(aF[3], wf, x23.y);
                        fma2(aF[4], wf, x45.x); fma2(aF[5], wf, x45.y);
                        fma2(aF[6], wf, x67.x); fma2(aF[7], wf, x67.y);
                        fma2(aG[0], wg, x01.x); fma2(aG[1], wg, x01.y);
                        fma2(aG[2], wg, x23.x); fma2(aG[3], wg, x23.y);
                        fma2(aG[4], wg, x45.x); fma2(aG[5], wg, x45.y);
                        fma2(aG[6], wg, x67.x); fma2(aG[7], wg, x67.y);
                        fma2(aO[0], wo, x01.x); fma2(aO[1], wo, x01.y);
                        fma2(aO[2], wo, x23.x); fma2(aO[3], wo, x23.y);
                        fma2(aO[4], wo, x45.x); fma2(aO[5], wo, x45.y);
                        fma2(aO[6], wo, x67.x); fma2(aO[7], wo, x67.y);
                    }
                }

                const float* buf = (c & 1) ? bufB : bufA;
#pragma unroll 2
                for (int kk = 0; kk < 4; ++kk) {
                    float4 wI = *(const float4*)(buf + (jh      ) * 20 + kk * 4);
                    float4 wF = *(const float4*)(buf + (jh + 128) * 20 + kk * 4);
                    float4 wG = *(const float4*)(buf + (jh + 256) * 20 + kk * 4);
                    float4 wO = *(const float4*)(buf + (jh + 384) * 20 + kk * 4);
                    const float* hb = hT + (c * 16 + kk * 4) * 36 + mg * 16;
#pragma unroll
                    for (int q = 0; q < 4; ++q) {
                        const ulonglong2* hp = (const ulonglong2*)(hb + q * 36);
                        ulonglong2 h01 = hp[0], h23 = hp[1], h45 = hp[2], h67 = hp[3];
                        float wIq = (q == 0) ? wI.x : (q == 1) ? wI.y : (q == 2) ? wI.z : wI.w;
                        float wFq = (q == 0) ? wF.x : (q == 1) ? wF.y : (q == 2) ? wF.z : wF.w;
                        float wGq = (q == 0) ? wG.x : (q == 1) ? wG.y : (q == 2) ? wG.z : wG.w;
                        float wOq = (q == 0) ? wO.x : (q == 1) ? wO.y : (q == 2) ? wO.z : wO.w;
                        u64 wi = dup2(wIq), wf = dup2(wFq), wg = dup2(wGq), wo = dup2(wOq);
                        fma2(aI[0], wi, h01.x); fma2(aI[1], wi, h01.y);
                        fma2(aI[2], wi, h23.x); fma2(aI[3], wi, h23.y);
                        fma2(aI[4], wi, h45.x); fma2(aI[5], wi, h45.y);
                        fma2(aI[6], wi, h67.x); fma2(aI[7], wi, h67.y);
                        fma2(aF[0], wf, h01.x); fma2(aF[1], wf, h01.y);
                        fma2(aF[2], wf, h23.x); fma2(aF[3], wf, h23.y);
                        fma2(aF[4], wf, h45.x); fma2(aF[5], wf, h45.y);
                        fma2(aF[6], wf, h67.x); fma2(aF[7], wf, h67.y);
                        fma2(aG[0], wg, h01.x); fma2(aG[1], wg, h01.y);
                        fma2(aG[2], wg, h23.x); fma2(aG[3], wg, h23.y);
                        fma2(aG[4], wg, h45.x); fma2(aG[5], wg, h45.y);
                        fma2(aG[6], wg, h67.x); fma2(aG[7], wg, h67.y);
                        fma2(aO[0], wo, h01.x); fma2(aO[1], wo, h01.y);
                        fma2(aO[2], wo, h23.x); fma2(aO[3], wo, h23.y);
                        fma2(aO[4], wo, h45.x); fma2(aO[5], wo, h45.y);
                        fma2(aO[6], wo, h67.x); fma2(aO[7], wo, h67.y);
                    }
                }
                // no trailing barrier — next chunk's top barrier covers reuse
            }

            __syncthreads();   // all hT(t-1) readers done before update writes hT(t)

#pragma unroll
            for (int p = 0; p < 8; ++p) {
                float i0, i1, f0, f1, g0, g1, o0, o1;
                unp2(aI[p], i0, i1);
                unp2(aF[p], f0, f1);
                unp2(aG[p], g0, g1);
                unp2(aO[p], o0, o1);
#pragma unroll
                for (int e = 0; e < 2; ++e) {
                    int sloc = p * 2 + e;
                    int m = mg * 16 + sloc;
                    float gi = e ? i1 : i0, gf = e ? f1 : f0;
                    float gg = e ? g1 : g0, go = e ? o1 : o0;
                    float iv = sigfast(gi), fv = sigfast(gf);
                    float gv = tanhfast(gg), ov = sigfast(go);
                    float cv = fmaf(fv, creg[sloc], iv * gv);
                    creg[sloc] = cv;
                    float hv = ov * tanhfast(cv);
                    hT[jh * 36 + m] = hv;
                    if (t == sNobs[m] - 1) g_hout[sSamp[m] * HID + jh] = hv;
                }
            }
            // next step's chunk-0 top barrier publishes hT(t)
        }

        CP_WAIT0();
        __syncthreads();

        // ================= head =================
        float* sWts  = sm + O_WTS;
        float* sXcat = sm + O_XCAT;
        float* sWc2  = sm + O_WC2;
        float* sC1o  = sm + O_C1;

#pragma unroll
        for (int q = 0; q < 17; ++q) {
            int idx = q * NTHREADS + tid;
            if (idx < 128 * 32) {
                int r = idx >> 5, cc = idx & 31;
                *(float4*)(sWts + r * 132 + cc * 4) = *(const float4*)(W_ts + r * HID + cc * 4);
            }
        }
        for (int idx = tid; idx < NACT * 32; idx += NTHREADS) {
            int o = idx >> 5, kb = (idx & 31) * 4;
            *(float4*)(sWc2 + o * 132 + kb) = *(const float4*)(W_c2 + o * HID + kb);
        }
        __syncthreads();

        // x_OS = relu(s_OS @ W_os^T + b_os)
        {
            float wos[8];
#pragma unroll
            for (int i = 0; i < 8; ++i) wos[i] = W_os[jh * 8 + i];
            float bos = b_os[jh];
#pragma unroll
            for (int mm = 0; mm < 16; ++mm) {
                int m = mg * 16 + mm;
                const float4* sp = (const float4*)(s + sSamp[m] * SDIM);
                float4 s0 = sp[0], s1 = sp[1];
                float a = bos;
                a = fmaf(wos[0], s0.x, a); a = fmaf(wos[1], s0.y, a);
                a = fmaf(wos[2], s0.z, a); a = fmaf(wos[3], s0.w, a);
                a = fmaf(wos[4], s1.x, a); a = fmaf(wos[5], s1.y, a);
                a = fmaf(wos[6], s1.z, a); a = fmaf(wos[7], s1.w, a);
                sXcat[m * 256 + jh] = fmaxf(a, 0.0f);
            }
        }
        // x_TS = relu(hout @ W_ts^T + b_ts)
        {
            float a16[16];
#pragma unroll
            for (int mm = 0; mm < 16; ++mm) a16[mm] = 0.0f;
#pragma unroll 1
            for (int k4 = 0; k4 < 32; ++k4) {
                float4 w = *(const float4*)(sWts + jh * 132 + k4 * 4);
#pragma unroll
                for (int mm = 0; mm < 16; ++mm) {
                    int m = mg * 16 + mm;
                    float4 h = *(const float4*)(g_hout + sSamp[m] * HID + k4 * 4);
                    float a = a16[mm];
                    a = fmaf(w.x, h.x, a);
                    a = fmaf(w.y, h.y, a);
                    a = fmaf(w.z, h.z, a);
                    a = fmaf(w.w, h.w, a);
                    a16[mm] = a;
                }
            }
            float bts = b_ts[jh];
#pragma unroll
            for (int mm = 0; mm < 16; ++mm) {
                int m = mg * 16 + mm;
                sXcat[m * 256 + HID + jh] = fmaxf(a16[mm] + bts, 0.0f);
            }
        }
        __syncthreads();

        // c1 = relu(xcat @ W_c1^T + b_c1), two staged halves
        {
            float a16[16];
#pragma unroll
            for (int mm = 0; mm < 16; ++mm) a16[mm] = 0.0f;
#pragma unroll 1
            for (int half = 0; half < 2; ++half) {
                __syncthreads();
#pragma unroll
                for (int q = 0; q < 17; ++q) {
                    int idx = q * NTHREADS + tid;
                    if (idx < 128 * 32) {
                        int r = idx >> 5, cc = idx & 31;
                        *(float4*)(sWts + r * 132 + cc * 4) =
                            *(const float4*)(W_c1 + r * 256 + half * 128 + cc * 4);
                    }
                }
                __syncthreads();
#pragma unroll 1
                for (int k4 = 0; k4 < 32; ++k4) {
                    float4 w = *(const float4*)(sWts + jh * 132 + k4 * 4);
#pragma unroll
                    for (int mm = 0; mm < 16; ++mm) {
                        int m = mg * 16 + mm;
                        float4 x = *(const float4*)(sXcat + m * 256 + half * 128 + k4 * 4);
                        float a = a16[mm];
                        a = fmaf(w.x, x.x, a);
                        a = fmaf(w.y, x.y, a);
                        a = fmaf(w.z, x.z, a);
                        a = fmaf(w.w, x.w, a);
                        a16[mm] = a;
                    }
                }
            }
            __syncthreads();   // xcat reads done before C1 overlays it
            float bc1 = b_c1[jh];
#pragma unroll
            for (int mm = 0; mm < 16; ++mm) {
                int m = mg * 16 + mm;
                sC1o[m * 132 + jh] = fmaxf(a16[mm] + bc1, 0.0f);
            }
        }
        __syncthreads();

        // out = c1 @ W_c2^T + b_c2
        for (int idx = tid; idx < M_TILE * NACT; idx += NTHREADS) {
            int m = idx / NACT, o = idx - m * NACT;
            float a = b_c2[o];
#pragma unroll 1
            for (int k4 = 0; k4 < 32; ++k4) {
                float4 w = *(const float4*)(sWc2 + o * 132 + k4 * 4);
                float4 x = *(const float4*)(sC1o + m * 132 + k4 * 4);
                a = fmaf(w.x, x.x, a);
                a = fmaf(w.y, x.y, a);
                a = fmaf(w.z, x.z, a);
                a = fmaf(w.w, x.w, a);
            }
            out[sSamp[m] * NACT + o] = a;
        }
        // tile-loop top barrier guards smem reuse
    }
}

// ---------------- launch ----------------
extern "C" void kernel_launch(void* const* d_in, const int* in_sizes, int n_in,
                              void* d_out, int out_size) {
    const float* s    = (const float*)d_in[0];
    const float* W_os = (const float*)d_in[1];
    const float* b_os = (const float*)d_in[2];
    const float* W_ih = (const float*)d_in[3];
    const float* W_hh = (const float*)d_in[4];
    const float* b_ih = (const float*)d_in[5];
    const float* b_hh = (const float*)d_in[6];
    const float* W_ts = (const float*)d_in[7];
    const float* b_ts = (const float*)d_in[8];
    const float* W_c1 = (const float*)d_in[9];
    const float* b_c1 = (const float*)d_in[10];
    const float* W_c2 = (const float*)d_in[11];
    const float* b_c2 = (const float*)d_in[12];
    float* out = (float*)d_out;

    cudaFuncSetAttribute(k_main, cudaFuncAttributeMaxDynamicSharedMemorySize, SMEM_BYTES);

    k_count<<<B_TOT / 256, 256>>>(s);
    k_prefix<<<1, 1>>>();
    k_scatter<<<B_TOT / 256, 256>>>();
    k_main<<<NPERSIST, NTHREADS, SMEM_BYTES>>>(s, W_os, b_os, W_ih, W_hh, b_ih, b_hh,
                                               W_ts, b_ts, W_c1, b_c1, W_c2, b_c2, out);
}

// round 15
// speedup vs baseline: 1.0928x; 1.0372x over previous
#include <cuda_runtime.h>
#include <math.h>
#include <cstdint>

#define B_TOT   32768
#define T_STEPS 32
#define HID     128
#define OBS_OS  8
#define OBS_TS  6
#define SDIM    200
#define NACT    9
#define M_TILE  64
#define NTHREADS 512
#define NTILES  (B_TOT / M_TILE)
#define NPERSIST 148               // 1 CTA per SM, persistent

typedef unsigned long long u64;

// ---------------- scratch ----------------
__device__ int   g_nobs[B_TOT];
__device__ int   g_perm[B_TOT];
__device__ int   g_hist[T_STEPS + 1];
__device__ int   g_cursor[T_STEPS + 1];
__device__ int   g_tile;
__device__ float g_hout[B_TOT * HID];     // h snapshot (16 MB static scratch)

// ---------------- shared layout (float offsets), total 49584 fl = 193.7 KB ----------------
#define O_BUFA  0                  // W chunk buf A [512][36] (32 K + pad)
#define O_BUFB  18432              // W chunk buf B [512][36]
#define O_WIH   36864              // W_ih [512][6]
#define O_HT    39936              // hT [k=128][68] (m contiguous, 64 samples + pad)
#define O_SX    48640              // xT double buffer 2 x [6][68]
#define O_INT   49456              // nobs[64], samp[64]
#define SMEM_FLOATS 49584
#define SMEM_BYTES  (SMEM_FLOATS * 4)
// head overlays (sSamp/sNobs preserved at O_INT)
#define O_WTS   0                  // [128][132] = 16896 (in bufA)
#define O_XCAT  18432              // [64][256] = 16384 (in bufB) -> ends 34816
#define O_WC2   34816              // [9][132]  = 1188  -> 36004 (<= 36864)
#define O_C1    36864              // [64][132] = 8448  -> 45312 (<= 48640)

// ---------------- helpers ----------------
__device__ __forceinline__ unsigned smem_u32(const void* p) {
    unsigned r;
    asm("{ .reg .u64 t; cvta.to.shared.u64 t, %1; cvt.u32.u64 %0, t; }" : "=r"(r) : "l"(p));
    return r;
}
__device__ __forceinline__ void cpa16(unsigned dst, const void* src) {
    asm volatile("cp.async.cg.shared.global [%0], [%1], 16;" :: "r"(dst), "l"(src));
}
__device__ __forceinline__ void cpa4(unsigned dst, const void* src) {
    asm volatile("cp.async.ca.shared.global [%0], [%1], 4;" :: "r"(dst), "l"(src));
}
#define CP_COMMIT()  asm volatile("cp.async.commit_group;" ::: "memory")
#define CP_WAIT0()   asm volatile("cp.async.wait_group 0;" ::: "memory")

__device__ __forceinline__ void fma2(u64 &d, u64 a, u64 b) {
    asm("fma.rn.f32x2 %0, %1, %2, %0;" : "+l"(d) : "l"(a), "l"(b));
}
__device__ __forceinline__ u64 dup2(float a) {
    u64 r; asm("mov.b64 %0, {%1, %1};" : "=l"(r) : "f"(a)); return r;
}
__device__ __forceinline__ void unp2(u64 v, float &lo, float &hi) {
    asm("mov.b64 {%0, %1}, %2;" : "=f"(lo), "=f"(hi) : "l"(v));
}
__device__ __forceinline__ float tanhfast(float x) {
    float y; asm("tanh.approx.f32 %0, %1;" : "=f"(y) : "f"(x)); return y;
}
__device__ __forceinline__ float sigfast(float x) {
    return fmaf(tanhfast(0.5f * x), 0.5f, 0.5f);
}

// ---------------- pre-pass ----------------
__global__ void k_count(const float* __restrict__ s) {
    int m = blockIdx.x * blockDim.x + threadIdx.x;
    if (m >= B_TOT) return;
    const float* p = s + m * SDIM + OBS_OS;
    int cnt = 0;
#pragma unroll
    for (int t = 0; t < T_STEPS; ++t) {
        float v = p[t * OBS_TS];
        cnt += (v == v) ? 1 : 0;
    }
    g_nobs[m] = cnt;
    atomicAdd(&g_hist[cnt], 1);
    if (cnt == 0) {   // reference: x_TS forced to 0 for empty sequences
        float4 z = make_float4(0.f, 0.f, 0.f, 0.f);
        float4* d = (float4*)(g_hout + m * HID);
#pragma unroll
        for (int q = 0; q < HID / 4; ++q) d[q] = z;
    }
}

__global__ void k_prefix() {
    int off = 0;
    for (int len = T_STEPS; len >= 0; --len) {
        g_cursor[len] = off;
        off += g_hist[len];
        g_hist[len] = 0;
    }
    g_tile = 0;            // reset persistent-tile counter each replay
}

__global__ void k_scatter() {
    int m = blockIdx.x * blockDim.x + threadIdx.x;
    if (m >= B_TOT) return;
    int pos = atomicAdd(&g_cursor[g_nobs[m]], 1);
    g_perm[pos] = m;
}

// ---------------- fused persistent main kernel ----------------
__global__ void __launch_bounds__(NTHREADS, 1)
k_main(const float* __restrict__ s,
       const float* __restrict__ W_os, const float* __restrict__ b_os,
       const float* __restrict__ W_ih, const float* __restrict__ W_hh,
       const float* __restrict__ b_ih, const float* __restrict__ b_hh,
       const float* __restrict__ W_ts, const float* __restrict__ b_ts,
       const float* __restrict__ W_c1, const float* __restrict__ b_c1,
       const float* __restrict__ W_c2, const float* __restrict__ b_c2,
       float* __restrict__ out)
{
    extern __shared__ float sm[];
    float* bufA  = sm + O_BUFA;
    float* bufB  = sm + O_BUFB;
    float* sWih  = sm + O_WIH;
    float* hT    = sm + O_HT;
    float* sX    = sm + O_SX;
    int*   sNobs = (int*)(sm + O_INT);
    int*   sSamp = sNobs + M_TILE;
    __shared__ int sTmaxS;
    __shared__ int sTile;

    const unsigned uBufA = smem_u32(bufA);
    const unsigned uBufB = smem_u32(bufB);
    const unsigned uSX   = smem_u32(sX);

    const int tid = threadIdx.x;
    const int jh  = tid & 127;    // hidden unit (owns gate rows jh+128g)
    const int mg  = tid >> 7;     // sample quarter: 16 samples mg*16..+15

    // hoisted per-thread constants
    float biasv[4];
#pragma unroll
    for (int g = 0; g < 4; ++g)
        biasv[g] = b_ih[jh + 128 * g] + b_hh[jh + 128 * g];

    // stage W_ih once (persists across tiles; never overwritten in LSTM phase...
    // but head overlays O_C1 over it, so restage per tile below)

    for (;;) {
        if (tid == 0) sTile = atomicAdd(&g_tile, 1);
        __syncthreads();                 // publish sTile; prior tile smem reads done
        const int tile = sTile;
        if (tile >= NTILES) break;
        const int base = tile * M_TILE;

        if (tid < M_TILE) {
            int idx = g_perm[base + tid];
            sSamp[tid] = idx;
            sNobs[tid] = g_nobs[idx];
        }
        __syncthreads();                 // publish sSamp

        // prologue: chunk0 + xT(0)
#pragma unroll
        for (int q = 0; q < 8; ++q) {
            int lin = q * NTHREADS + tid;       // 0..4095 float4s
            int r = lin >> 3, cc = lin & 7;
            cpa16(uBufA + (unsigned)(r * 36 + cc * 4) * 4u,
                  W_hh + r * HID + 0 * 32 + cc * 4);
        }
        if (tid < M_TILE * OBS_TS) {            // 384 threads
            int m = tid / OBS_TS, i = tid - m * OBS_TS;
            cpa4(uSX + (unsigned)(i * 68 + m) * 4u,
                 s + sSamp[m] * SDIM + OBS_OS + 0 * OBS_TS + i);
        }
        CP_COMMIT();

        // stage W_ih + zero hT while prefetch flies
        for (int i = tid; i < 512 * OBS_TS; i += NTHREADS) sWih[i] = W_ih[i];
        for (int i = tid; i < 128 * 68; i += NTHREADS) hT[i] = 0.0f;
        if (tid == 0) {
            int tm = 0;
            for (int m = 0; m < M_TILE; ++m) tm = max(tm, sNobs[m]);
            sTmaxS = tm;
        }
        float creg[16];
#pragma unroll
        for (int e = 0; e < 16; ++e) creg[e] = 0.0f;

        __syncthreads();
        const int tmax = sTmaxS;

        // ================= LSTM recurrence =================
        for (int t = 0; t < tmax; ++t) {
            float* xTc = sX + (t & 1) * 408;

            u64 aI[8], aF[8], aG[8], aO[8];
            {
                u64 bi = dup2(biasv[0]), bf = dup2(biasv[1]);
                u64 bg = dup2(biasv[2]), bo = dup2(biasv[3]);
#pragma unroll
                for (int p = 0; p < 8; ++p) { aI[p] = bi; aF[p] = bf; aG[p] = bg; aO[p] = bo; }
            }

#pragma unroll
            for (int c = 0; c < 4; ++c) {
                CP_WAIT0();
                __syncthreads();      // chunk c visible; parity buffer reusable

                // distance-1 prefetch of chunk c+1 (wraps to next step's chunk0)
                {
                    int nc = (c + 1) & 3;
                    unsigned ubuf = ((c + 1) & 1) ? uBufB : uBufA;
#pragma unroll
                    for (int q = 0; q < 8; ++q) {
                        int lin = q * NTHREADS + tid;
                        int r = lin >> 3, cc2 = lin & 7;
                        cpa16(ubuf + (unsigned)(r * 36 + cc2 * 4) * 4u,
                              W_hh + r * HID + nc * 32 + cc2 * 4);
                    }
                    if (c == 3 && (t + 1) < tmax && tid < M_TILE * OBS_TS) {
                        int m = tid / OBS_TS, i = tid - m * OBS_TS;
                        cpa4(uSX + (unsigned)(((t + 1) & 1) * 408 + i * 68 + m) * 4u,
                             s + sSamp[m] * SDIM + OBS_OS + (t + 1) * OBS_TS + i);
                    }
                    CP_COMMIT();
                }

                if (c == 0) {
                    // sanitize xT(t): NaN -> 0 (published by c==1's top barrier)
                    if (tid < M_TILE * OBS_TS) {
                        int m = tid / OBS_TS, i = tid - m * OBS_TS;
                        float v = xTc[i * 68 + m];
                        xTc[i * 68 + m] = (v == v) ? v : 0.0f;
                    }
                }
                if (c == 1) {
                    // x contribution
#pragma unroll
                    for (int i = 0; i < OBS_TS; ++i) {
                        u64 wi = dup2(sWih[(jh      ) * 6 + i]);
                        u64 wf = dup2(sWih[(jh + 128) * 6 + i]);
                        u64 wg = dup2(sWih[(jh + 256) * 6 + i]);
                        u64 wo = dup2(sWih[(jh + 384) * 6 + i]);
                        const ulonglong2* xp = (const ulonglong2*)(xTc + i * 68 + mg * 16);
                        ulonglong2 x01 = xp[0], x23 = xp[1], x45 = xp[2], x67 = xp[3];
                        fma2(aI[0], wi, x01.x); fma2(aI[1], wi, x01.y);
                        fma2(aI[2], wi, x23.x); fma2(aI[3], wi, x23.y);
                        fma2(aI[4], wi, x45.x); fma2(aI[5], wi, x45.y);
                        fma2(aI[6], wi, x67.x); fma2(aI[7], wi, x67.y);
                        fma2(aF[0], wf, x01.x); fma2(aF[1], wf, x01.y);
                        fma2(aF[2], wf, x23.x); fma2(aF[3], wf, x23.y);
                        fma2(aF[4], wf, x45.x); fma2(aF[5], wf, x45.y);
                        fma2(aF[6], wf, x67.x); fma2(aF[7], wf, x67.y);
                        fma2(aG[0], wg, x01.x); fma2(aG[1], wg, x01.y);
                        fma2(aG[2], wg, x23.x); fma2(aG[3], wg, x23.y);
                        fma2(aG[4], wg, x45.x); fma2(aG[5], wg, x45.y);
                        fma2(aG[6], wg, x67.x); fma2(aG[7], wg, x67.y);
                        fma2(aO[0], wo, x01.x); fma2(aO[1], wo, x01.y);
                        fma2(aO[2], wo, x23.x); fma2(aO[3], wo, x23.y);
                        fma2(aO[4], wo, x45.x); fma2(aO[5], wo, x45.y);
                        fma2(aO[6], wo, x67.x); fma2(aO[7], wo, x67.y);
                    }
                }

                const float* buf = (c & 1) ? bufB : bufA;
#pragma unroll 2
                for (int kk = 0; kk < 8; ++kk) {
                    float4 wI = *(const float4*)(buf + (jh      ) * 36 + kk * 4);
                    float4 wF = *(const float4*)(buf + (jh + 128) * 36 + kk * 4);
                    float4 wG = *(const float4*)(buf + (jh + 256) * 36 + kk * 4);
                    float4 wO = *(const float4*)(buf + (jh + 384) * 36 + kk * 4);
                    const float* hb = hT + (c * 32 + kk * 4) * 68 + mg * 16;
#pragma unroll
                    for (int q = 0; q < 4; ++q) {
                        const ulonglong2* hp = (const ulonglong2*)(hb + q * 68);
                        ulonglong2 h01 = hp[0], h23 = hp[1], h45 = hp[2], h67 = hp[3];
                        float wIq = (q == 0) ? wI.x : (q == 1) ? wI.y : (q == 2) ? wI.z : wI.w;
                        float wFq = (q == 0) ? wF.x : (q == 1) ? wF.y : (q == 2) ? wF.z : wF.w;
                        float wGq = (q == 0) ? wG.x : (q == 1) ? wG.y : (q == 2) ? wG.z : wG.w;
                        float wOq = (q == 0) ? wO.x : (q == 1) ? wO.y : (q == 2) ? wO.z : wO.w;
                        u64 wi = dup2(wIq), wf = dup2(wFq), wg = dup2(wGq), wo = dup2(wOq);
                        fma2(aI[0], wi, h01.x); fma2(aI[1], wi, h01.y);
                        fma2(aI[2], wi, h23.x); fma2(aI[3], wi, h23.y);
                        fma2(aI[4], wi, h45.x); fma2(aI[5], wi, h45.y);
                        fma2(aI[6], wi, h67.x); fma2(aI[7], wi, h67.y);
                        fma2(aF[0], wf, h01.x); fma2(aF[1], wf, h01.y);
                        fma2(aF[2], wf, h23.x); fma2(aF[3], wf, h23.y);
                        fma2(aF[4], wf, h45.x); fma2(aF[5], wf, h45.y);
                        fma2(aF[6], wf, h67.x); fma2(aF[7], wf, h67.y);
                        fma2(aG[0], wg, h01.x); fma2(aG[1], wg, h01.y);
                        fma2(aG[2], wg, h23.x); fma2(aG[3], wg, h23.y);
                        fma2(aG[4], wg, h45.x); fma2(aG[5], wg, h45.y);
                        fma2(aG[6], wg, h67.x); fma2(aG[7], wg, h67.y);
                        fma2(aO[0], wo, h01.x); fma2(aO[1], wo, h01.y);
                        fma2(aO[2], wo, h23.x); fma2(aO[3], wo, h23.y);
                        fma2(aO[4], wo, h45.x); fma2(aO[5], wo, h45.y);
                        fma2(aO[6], wo, h67.x); fma2(aO[7], wo, h67.y);
                    }
                }
                // no trailing barrier — next chunk's top barrier covers reuse
            }

            __syncthreads();   // all hT(t-1) readers done before update writes hT(t)

#pragma unroll
            for (int p = 0; p < 8; ++p) {
                float i0, i1, f0, f1, g0, g1, o0, o1;
                unp2(aI[p], i0, i1);
                unp2(aF[p], f0, f1);
                unp2(aG[p], g0, g1);
                unp2(aO[p], o0, o1);
#pragma unroll
                for (int e = 0; e < 2; ++e) {
                    int sloc = p * 2 + e;
                    int m = mg * 16 + sloc;
                    float gi = e ? i1 : i0, gf = e ? f1 : f0;
                    float gg = e ? g1 : g0, go = e ? o1 : o0;
                    float iv = sigfast(gi), fv = sigfast(gf);
                    float gv = tanhfast(gg), ov = sigfast(go);
                    float cv = fmaf(fv, creg[sloc], iv * gv);
                    creg[sloc] = cv;
                    float hv = ov * tanhfast(cv);
                    hT[jh * 68 + m] = hv;
                    if (t == sNobs[m] - 1) g_hout[sSamp[m] * HID + jh] = hv;
                }
            }
            // next step's chunk-0 top barrier publishes hT(t)
        }

        CP_WAIT0();
        __syncthreads();

        // ================= head (64 samples) =================
        float* sWts  = sm + O_WTS;
        float* sXcat = sm + O_XCAT;
        float* sWc2  = sm + O_WC2;
        float* sC1o  = sm + O_C1;

        // stage W_ts [128][132] : 4096 float4, exactly 8 per thread
#pragma unroll
        for (int q = 0; q < 8; ++q) {
            int idx = q * NTHREADS + tid;
            int r = idx >> 5, cc = idx & 31;
            *(float4*)(sWts + r * 132 + cc * 4) = *(const float4*)(W_ts + r * HID + cc * 4);
        }
        for (int idx = tid; idx < NACT * 32; idx += NTHREADS) {
            int o = idx >> 5, kb = (idx & 31) * 4;
            *(float4*)(sWc2 + o * 132 + kb) = *(const float4*)(W_c2 + o * HID + kb);
        }
        __syncthreads();

        // x_OS = relu(s_OS @ W_os^T + b_os)
        {
            float wos[8];
#pragma unroll
            for (int i = 0; i < 8; ++i) wos[i] = W_os[jh * 8 + i];
            float bos = b_os[jh];
#pragma unroll
            for (int mm = 0; mm < 16; ++mm) {
                int m = mg * 16 + mm;
                const float4* sp = (const float4*)(s + sSamp[m] * SDIM);
                float4 s0 = sp[0], s1 = sp[1];
                float a = bos;
                a = fmaf(wos[0], s0.x, a); a = fmaf(wos[1], s0.y, a);
                a = fmaf(wos[2], s0.z, a); a = fmaf(wos[3], s0.w, a);
                a = fmaf(wos[4], s1.x, a); a = fmaf(wos[5], s1.y, a);
                a = fmaf(wos[6], s1.z, a); a = fmaf(wos[7], s1.w, a);
                sXcat[m * 256 + jh] = fmaxf(a, 0.0f);
            }
        }
        // x_TS = relu(hout @ W_ts^T + b_ts)
        {
            float a16[16];
#pragma unroll
            for (int mm = 0; mm < 16; ++mm) a16[mm] = 0.0f;
#pragma unroll 1
            for (int k4 = 0; k4 < 32; ++k4) {
                float4 w = *(const float4*)(sWts + jh * 132 + k4 * 4);
#pragma unroll
                for (int mm = 0; mm < 16; ++mm) {
                    int m = mg * 16 + mm;
                    float4 h = *(const float4*)(g_hout + sSamp[m] * HID + k4 * 4);
                    float a = a16[mm];
                    a = fmaf(w.x, h.x, a);
                    a = fmaf(w.y, h.y, a);
                    a = fmaf(w.z, h.z, a);
                    a = fmaf(w.w, h.w, a);
                    a16[mm] = a;
                }
            }
            float bts = b_ts[jh];
#pragma unroll
            for (int mm = 0; mm < 16; ++mm) {
                int m = mg * 16 + mm;
                sXcat[m * 256 + HID + jh] = fmaxf(a16[mm] + bts, 0.0f);
            }
        }
        __syncthreads();

        // c1 = relu(xcat @ W_c1^T + b_c1), two staged halves
        {
            float a16[16];
#pragma unroll
            for (int mm = 0; mm < 16; ++mm) a16[mm] = 0.0f;
#pragma unroll 1
            for (int half = 0; half < 2; ++half) {
                __syncthreads();
#pragma unroll
                for (int q = 0; q < 8; ++q) {
                    int idx = q * NTHREADS + tid;
                    int r = idx >> 5, cc = idx & 31;
                    *(float4*)(sWts + r * 132 + cc * 4) =
                        *(const float4*)(W_c1 + r * 256 + half * 128 + cc * 4);
                }
                __syncthreads();
#pragma unroll 1
                for (int k4 = 0; k4 < 32; ++k4) {
                    float4 w = *(const float4*)(sWts + jh * 132 + k4 * 4);
#pragma unroll
                    for (int mm = 0; mm < 16; ++mm) {
                        int m = mg * 16 + mm;
                        float4 x = *(const float4*)(sXcat + m * 256 + half * 128 + k4 * 4);
                        float a = a16[mm];
                        a = fmaf(w.x, x.x, a);
                        a = fmaf(w.y, x.y, a);
                        a = fmaf(w.z, x.z, a);
                        a = fmaf(w.w, x.w, a);
                        a16[mm] = a;
                    }
                }
            }
            __syncthreads();   // xcat reads done (C1 region is separate, but keep ordering)
            float bc1 = b_c1[jh];
#pragma unroll
            for (int mm = 0; mm < 16; ++mm) {
                int m = mg * 16 + mm;
                sC1o[m * 132 + jh] = fmaxf(a16[mm] + bc1, 0.0f);
            }
        }
        __syncthreads();

        // out = c1 @ W_c2^T + b_c2 (576 outputs)
        for (int idx = tid; idx < M_TILE * NACT; idx += NTHREADS) {
            int m = idx / NACT, o = idx - m * NACT;
            float a = b_c2[o];
#pragma unroll 1
            for (int k4 = 0; k4 < 32; ++k4) {
                float4 w = *(const float4*)(sWc2 + o * 132 + k4 * 4);
                float4 x = *(const float4*)(sC1o + m * 132 + k4 * 4);
                a = fmaf(w.x, x.x, a);
                a = fmaf(w.y, x.y, a);
                a = fmaf(w.z, x.z, a);
                a = fmaf(w.w, x.w, a);
            }
            out[sSamp[m] * NACT + o] = a;
        }
        // tile-loop top barrier guards smem reuse
    }
}

// ---------------- launch ----------------
extern "C" void kernel_launch(void* const* d_in, const int* in_sizes, int n_in,
                              void* d_out, int out_size) {
    const float* s    = (const float*)d_in[0];
    const float* W_os = (const float*)d_in[1];
    const float* b_os = (const float*)d_in[2];
    const float* W_ih = (const float*)d_in[3];
    const float* W_hh = (const float*)d_in[4];
    const float* b_ih = (const float*)d_in[5];
    const float* b_hh = (const float*)d_in[6];
    const float* W_ts = (const float*)d_in[7];
    const float* b_ts = (const float*)d_in[8];
    const float* W_c1 = (const float*)d_in[9];
    const float* b_c1 = (const float*)d_in[10];
    const float* W_c2 = (const float*)d_in[11];
    const float* b_c2 = (const float*)d_in[12];
    float* out = (float*)d_out;

    cudaFuncSetAttribute(k_main, cudaFuncAttributeMaxDynamicSharedMemorySize, SMEM_BYTES);

    k_count<<<B_TOT / 256, 256>>>(s);
    k_prefix<<<1, 1>>>();
    k_scatter<<<B_TOT / 256, 256>>>();
    k_main<<<NPERSIST, NTHREADS, SMEM_BYTES>>>(s, W_os, b_os, W_ih, W_hh, b_ih, b_hh,
                                               W_ts, b_ts, W_c1, b_c1, W_c2, b_c2, out);
}

// round 17
// speedup vs baseline: 1.1218x; 1.0266x over previous
#include <cuda_runtime.h>
#include <math.h>
#include <cstdint>

#define B_TOT   32768
#define T_STEPS 32
#define HID     128
#define OBS_OS  8
#define OBS_TS  6
#define SDIM    200
#define NACT    9
#define M_TILE  64
#define NTHREADS 512
#define NTILES  (B_TOT / M_TILE)
#define NPERSIST 148               // 1 CTA per SM, persistent

typedef unsigned long long u64;

// ---------------- scratch ----------------
__device__ int   g_nobs[B_TOT];
__device__ int   g_perm[B_TOT];
__device__ int   g_hist[T_STEPS + 1];
__device__ int   g_cursor[T_STEPS + 1];
__device__ int   g_tile;
__device__ float g_hout[B_TOT * HID];     // h snapshot (16 MB static scratch)

// ---------------- shared layout (float offsets) ----------------
#define O_BUFA  0                  // W chunk buf A [512][36]
#define O_BUFB  18432              // W chunk buf B [512][36]
#define O_WIH   36864              // W_ih [512][6]
#define O_HT    39936              // hT [k=128][68]
#define O_SX    48640              // xT double buffer 2 x [6][68]
#define O_INT   49456              // nobs[64], samp[64]
#define O_MBAR  49584              // 4 mbarriers (u64): empty0,empty1,full0,full1
#define SMEM_FLOATS 49600
#define SMEM_BYTES  (SMEM_FLOATS * 4)
// head overlays (sSamp/sNobs/mbars preserved)
#define O_WTS   0                  // [128][132] = 16896 (in bufA)
#define O_XCAT  18432              // [64][256] = 16384 (in bufB) -> ends 34816
#define O_WC2   34816              // [9][132]  = 1188  -> 36004
#define O_C1    36864              // [64][132] = 8448  -> 45312

// ---------------- helpers ----------------
__device__ __forceinline__ unsigned smem_u32(const void* p) {
    unsigned r;
    asm("{ .reg .u64 t; cvta.to.shared.u64 t, %1; cvt.u32.u64 %0, t; }" : "=r"(r) : "l"(p));
    return r;
}
__device__ __forceinline__ void cpa16(unsigned dst, const void* src) {
    asm volatile("cp.async.cg.shared.global [%0], [%1], 16;" :: "r"(dst), "l"(src));
}
__device__ __forceinline__ void mbar_init(unsigned addr, unsigned cnt) {
    asm volatile("mbarrier.init.shared::cta.b64 [%0], %1;" :: "r"(addr), "r"(cnt) : "memory");
}
__device__ __forceinline__ void mbar_arrive(unsigned addr) {
    asm volatile("mbarrier.arrive.release.cta.shared::cta.b64 _, [%0];" :: "r"(addr) : "memory");
}
// .noinc: async arrival counts against the initialized expected count
// (the default variant increments expected-count first -> net zero -> deadlock; R16 bug)
__device__ __forceinline__ void cpasync_arrive(unsigned addr) {
    asm volatile("cp.async.mbarrier.arrive.noinc.shared::cta.b64 [%0];" :: "r"(addr) : "memory");
}
__device__ __forceinline__ void mbar_wait(unsigned addr, unsigned parity) {
    asm volatile(
        "{\n\t"
        ".reg .pred P;\n\t"
        "WAIT_LP_%=:\n\t"
        "mbarrier.try_wait.parity.acquire.cta.shared::cta.b64 P, [%0], %1, 0x989680;\n\t"
        "@P bra.uni WAIT_DN_%=;\n\t"
        "bra.uni WAIT_LP_%=;\n\t"
        "WAIT_DN_%=:\n\t"
        "}"
        :: "r"(addr), "r"(parity) : "memory");
}

__device__ __forceinline__ void fma2(u64 &d, u64 a, u64 b) {
    asm("fma.rn.f32x2 %0, %1, %2, %0;" : "+l"(d) : "l"(a), "l"(b));
}
__device__ __forceinline__ u64 dup2(float a) {
    u64 r; asm("mov.b64 %0, {%1, %1};" : "=l"(r) : "f"(a)); return r;
}
__device__ __forceinline__ void unp2(u64 v, float &lo, float &hi) {
    asm("mov.b64 {%0, %1}, %2;" : "=f"(lo), "=f"(hi) : "l"(v));
}
__device__ __forceinline__ float tanhfast(float x) {
    float y; asm("tanh.approx.f32 %0, %1;" : "=f"(y) : "f"(x)); return y;
}
__device__ __forceinline__ float sigfast(float x) {
    return fmaf(tanhfast(0.5f * x), 0.5f, 0.5f);
}

// ---------------- pre-pass ----------------
__global__ void k_count(const float* __restrict__ s) {
    int m = blockIdx.x * blockDim.x + threadIdx.x;
    if (m >= B_TOT) return;
    const float* p = s + m * SDIM + OBS_OS;
    int cnt = 0;
#pragma unroll
    for (int t = 0; t < T_STEPS; ++t) {
        float v = p[t * OBS_TS];
        cnt += (v == v) ? 1 : 0;
    }
    g_nobs[m] = cnt;
    atomicAdd(&g_hist[cnt], 1);
    if (cnt == 0) {   // reference: x_TS forced to 0 for empty sequences
        float4 z = make_float4(0.f, 0.f, 0.f, 0.f);
        float4* d = (float4*)(g_hout + m * HID);
#pragma unroll
        for (int q = 0; q < HID / 4; ++q) d[q] = z;
    }
}

__global__ void k_prefix() {
    int off = 0;
    for (int len = T_STEPS; len >= 0; --len) {
        g_cursor[len] = off;
        off += g_hist[len];
        g_hist[len] = 0;
    }
    g_tile = 0;
}

__global__ void k_scatter() {
    int m = blockIdx.x * blockDim.x + threadIdx.x;
    if (m >= B_TOT) return;
    int pos = atomicAdd(&g_cursor[g_nobs[m]], 1);
    g_perm[pos] = m;
}

// ---------------- fused persistent main kernel ----------------
__global__ void __launch_bounds__(NTHREADS, 1)
k_main(const float* __restrict__ s,
       const float* __restrict__ W_os, const float* __restrict__ b_os,
       const float* __restrict__ W_ih, const float* __restrict__ W_hh,
       const float* __restrict__ b_ih, const float* __restrict__ b_hh,
       const float* __restrict__ W_ts, const float* __restrict__ b_ts,
       const float* __restrict__ W_c1, const float* __restrict__ b_c1,
       const float* __restrict__ W_c2, const float* __restrict__ b_c2,
       float* __restrict__ out)
{
    extern __shared__ float sm[];
    float* bufA  = sm + O_BUFA;
    float* bufB  = sm + O_BUFB;
    float* sWih  = sm + O_WIH;
    float* hT    = sm + O_HT;
    float* sX    = sm + O_SX;
    int*   sNobs = (int*)(sm + O_INT);
    int*   sSamp = sNobs + M_TILE;
    __shared__ int sTmaxS;
    __shared__ int sTile;

    const unsigned uBufA = smem_u32(bufA);
    const unsigned uBufB = smem_u32(bufB);
    const unsigned uMB   = smem_u32(sm + O_MBAR);   // empty0,empty1,full0,full1 (8B each)

    const int tid = threadIdx.x;
    const int jh  = tid & 127;
    const int mg  = tid >> 7;
    const int xm  = tid / OBS_TS;            // x staging sample
    const int xi  = tid - xm * OBS_TS;       // x staging feature
    const bool xthr = (tid < M_TILE * OBS_TS);

    float biasv[4];
#pragma unroll
    for (int g = 0; g < 4; ++g)
        biasv[g] = b_ih[jh + 128 * g] + b_hh[jh + 128 * g];

    // ---- mbarrier setup (once) ----
    if (tid == 0) {
        mbar_init(uMB + 0,  NTHREADS);   // empty0
        mbar_init(uMB + 8,  NTHREADS);   // empty1
        mbar_init(uMB + 16, NTHREADS);   // full0
        mbar_init(uMB + 24, NTHREADS);   // full1
    }
    __syncthreads();
    mbar_arrive(uMB + 0);   // pre-arm: both buffers start "empty" (phase 0 done)
    mbar_arrive(uMB + 8);
    int G = 0;              // global chunk counter (multiple of 4 at tile starts)

    for (;;) {
        if (tid == 0) sTile = atomicAdd(&g_tile, 1);
        __syncthreads();
        const int tile = sTile;
        if (tile >= NTILES) break;
        const int base = tile * M_TILE;

        if (tid < M_TILE) {
            int idx = g_perm[base + tid];
            sSamp[tid] = idx;
            sNobs[tid] = g_nobs[idx];
        }
        __syncthreads();
        if (tid == 0) {
            int tm = 0;
            for (int m = 0; m < M_TILE; ++m) tm = max(tm, sNobs[m]);
            sTmaxS = tm;
        }
        __syncthreads();
        const int tmax = sTmaxS;
        if (tmax == 0) {
            // no LSTM work; g_hout rows already zeroed in k_count
        } else {
            // ---- stage chunk G (W chunk 0) ----
            {
                unsigned eb = uMB + (unsigned)(G & 1) * 8u;
                unsigned fb = uMB + 16u + (unsigned)(G & 1) * 8u;
                mbar_wait(eb, (unsigned)((G >> 1) & 1));
                unsigned ubuf = (G & 1) ? uBufB : uBufA;
#pragma unroll
                for (int q = 0; q < 8; ++q) {
                    int lin = q * NTHREADS + tid;
                    int r = lin >> 3, cc = lin & 7;
                    cpa16(ubuf + (unsigned)(r * 36 + cc * 4) * 4u,
                          W_hh + r * HID + 0 * 32 + cc * 4);
                }
                cpasync_arrive(fb);
            }
            // stage x(0) via LDG (sanitized), stage W_ih, zero hT
            if (xthr) {
                float v = s[sSamp[xm] * SDIM + OBS_OS + xi];
                sX[xi * 68 + xm] = (v == v) ? v : 0.0f;
            }
            for (int i = tid; i < 512 * OBS_TS; i += NTHREADS) sWih[i] = W_ih[i];
            for (int i = tid; i < 128 * 68; i += NTHREADS) hT[i] = 0.0f;
            float creg[16];
#pragma unroll
            for (int e = 0; e < 16; ++e) creg[e] = 0.0f;
            __syncthreads();   // publish xT(0), sWih, hT zeros

            // ================= LSTM recurrence =================
            for (int t = 0; t < tmax; ++t) {
                float* xTc = sX + (t & 1) * 408;

                float xnext = 0.0f;
                const bool xload = xthr && (t + 1 < tmax);
                if (xload)
                    xnext = s[sSamp[xm] * SDIM + OBS_OS + (t + 1) * OBS_TS + xi];

                u64 aI[8], aF[8], aG[8], aO[8];
                {
                    u64 bi = dup2(biasv[0]), bf = dup2(biasv[1]);
                    u64 bg = dup2(biasv[2]), bo = dup2(biasv[3]);
#pragma unroll
                    for (int p = 0; p < 8; ++p) { aI[p] = bi; aF[p] = bf; aG[p] = bg; aO[p] = bo; }
                }

#pragma unroll
                for (int c = 0; c < 4; ++c) {
                    // stage chunk G+1 (unless last chunk of tile)
                    if (!((t == tmax - 1) && (c == 3))) {
                        int gn = G + 1;
                        unsigned eb = uMB + (unsigned)(gn & 1) * 8u;
                        unsigned fb = uMB + 16u + (unsigned)(gn & 1) * 8u;
                        mbar_wait(eb, (unsigned)((gn >> 1) & 1));
                        unsigned ubuf = (gn & 1) ? uBufB : uBufA;
                        int nc = gn & 3;
#pragma unroll
                        for (int q = 0; q < 8; ++q) {
                            int lin = q * NTHREADS + tid;
                            int r = lin >> 3, cc2 = lin & 7;
                            cpa16(ubuf + (unsigned)(r * 36 + cc2 * 4) * 4u,
                                  W_hh + r * HID + nc * 32 + cc2 * 4);
                        }
                        cpasync_arrive(fb);
                    }

                    // consume chunk G
                    mbar_wait(uMB + 16u + (unsigned)(G & 1) * 8u, (unsigned)((G >> 1) & 1));

                    if (c == 1) {
                        // x contribution
#pragma unroll
                        for (int i = 0; i < OBS_TS; ++i) {
                            u64 wi = dup2(sWih[(jh      ) * 6 + i]);
                            u64 wf = dup2(sWih[(jh + 128) * 6 + i]);
                            u64 wg = dup2(sWih[(jh + 256) * 6 + i]);
                            u64 wo = dup2(sWih[(jh + 384) * 6 + i]);
                            const ulonglong2* xp = (const ulonglong2*)(xTc + i * 68 + mg * 16);
                            ulonglong2 x01 = xp[0], x23 = xp[1], x45 = xp[2], x67 = xp[3];
                            fma2(aI[0], wi, x01.x); fma2(aI[1], wi, x01.y);
                            fma2(aI[2], wi, x23.x); fma2(aI[3], wi, x23.y);
                            fma2(aI[4], wi, x45.x); fma2(aI[5], wi, x45.y);
                            fma2(aI[6], wi, x67.x); fma2(aI[7], wi, x67.y);
                            fma2(aF[0], wf, x01.x); fma2(aF[1], wf, x01.y);
                            fma2(aF[2], wf, x23.x); fma2(aF[3], wf, x23.y);
                            fma2(aF[4], wf, x45.x); fma2(aF[5], wf, x45.y);
                            fma2(aF[6], wf, x67.x); fma2(aF[7], wf, x67.y);
                            fma2(aG[0], wg, x01.x); fma2(aG[1], wg, x01.y);
                            fma2(aG[2], wg, x23.x); fma2(aG[3], wg, x23.y);
                            fma2(aG[4], wg, x45.x); fma2(aG[5], wg, x45.y);
                            fma2(aG[6], wg, x67.x); fma2(aG[7], wg, x67.y);
                            fma2(aO[0], wo, x01.x); fma2(aO[1], wo, x01.y);
                            fma2(aO[2], wo, x23.x); fma2(aO[3], wo, x23.y);
                            fma2(aO[4], wo, x45.x); fma2(aO[5], wo, x45.y);
                            fma2(aO[6], wo, x67.x); fma2(aO[7], wo, x67.y);
                        }
                    }

                    const float* buf = (G & 1) ? bufB : bufA;
#pragma unroll 2
                    for (int kk = 0; kk < 8; ++kk) {
                        float4 wI = *(const float4*)(buf + (jh      ) * 36 + kk * 4);
                        float4 wF = *(const float4*)(buf + (jh + 128) * 36 + kk * 4);
                        float4 wG = *(const float4*)(buf + (jh + 256) * 36 + kk * 4);
                        float4 wO = *(const float4*)(buf + (jh + 384) * 36 + kk * 4);
                        const float* hb = hT + (c * 32 + kk * 4) * 68 + mg * 16;
#pragma unroll
                        for (int q = 0; q < 4; ++q) {
                            const ulonglong2* hp = (const ulonglong2*)(hb + q * 68);
                            ulonglong2 h01 = hp[0], h23 = hp[1], h45 = hp[2], h67 = hp[3];
                            float wIq = (q == 0) ? wI.x : (q == 1) ? wI.y : (q == 2) ? wI.z : wI.w;
                            float wFq = (q == 0) ? wF.x : (q == 1) ? wF.y : (q == 2) ? wF.z : wF.w;
                            float wGq = (q == 0) ? wG.x : (q == 1) ? wG.y : (q == 2) ? wG.z : wG.w;
                            float wOq = (q == 0) ? wO.x : (q == 1) ? wO.y : (q == 2) ? wO.z : wO.w;
                            u64 wi = dup2(wIq), wf = dup2(wFq), wg = dup2(wGq), wo = dup2(wOq);
                            fma2(aI[0], wi, h01.x); fma2(aI[1], wi, h01.y);
                            fma2(aI[2], wi, h23.x); fma2(aI[3], wi, h23.y);
                            fma2(aI[4], wi, h45.x); fma2(aI[5], wi, h45.y);
                            fma2(aI[6], wi, h67.x); fma2(aI[7], wi, h67.y);
                            fma2(aF[0], wf, h01.x); fma2(aF[1], wf, h01.y);
                            fma2(aF[2], wf, h23.x); fma2(aF[3], wf, h23.y);
                            fma2(aF[4], wf, h45.x); fma2(aF[5], wf, h45.y);
                            fma2(aF[6], wf, h67.x); fma2(aF[7], wf, h67.y);
                            fma2(aG[0], wg, h01.x); fma2(aG[1], wg, h01.y);
                            fma2(aG[2], wg, h23.x); fma2(aG[3], wg, h23.y);
                            fma2(aG[4], wg, h45.x); fma2(aG[5], wg, h45.y);
                            fma2(aG[6], wg, h67.x); fma2(aG[7], wg, h67.y);
                            fma2(aO[0], wo, h01.x); fma2(aO[1], wo, h01.y);
                            fma2(aO[2], wo, h23.x); fma2(aO[3], wo, h23.y);
                            fma2(aO[4], wo, h45.x); fma2(aO[5], wo, h45.y);
                            fma2(aO[6], wo, h67.x); fma2(aO[7], wo, h67.y);
                        }
                    }
                    mbar_arrive(uMB + (unsigned)(G & 1) * 8u);   // done reading buf
                    ++G;
                }

                // publish x(t+1) before step barrier
                if (xload) {
                    xnext = (xnext == xnext) ? xnext : 0.0f;
                    sX[((t + 1) & 1) * 408 + xi * 68 + xm] = xnext;
                }
                __syncthreads();   // all hT(t-1) readers done + xT(t+1) published

#pragma unroll
                for (int p = 0; p < 8; ++p) {
                    float i0, i1, f0, f1, g0, g1, o0, o1;
                    unp2(aI[p], i0, i1);
                    unp2(aF[p], f0, f1);
                    unp2(aG[p], g0, g1);
                    unp2(aO[p], o0, o1);
#pragma unroll
                    for (int e = 0; e < 2; ++e) {
                        int sloc = p * 2 + e;
                        int m = mg * 16 + sloc;
                        float gi = e ? i1 : i0, gf = e ? f1 : f0;
                        float gg = e ? g1 : g0, go = e ? o1 : o0;
                        float iv = sigfast(gi), fv = sigfast(gf);
                        float gv = tanhfast(gg), ov = sigfast(go);
                        float cv = fmaf(fv, creg[sloc], iv * gv);
                        creg[sloc] = cv;
                        float hv = ov * tanhfast(cv);
                        hT[jh * 68 + m] = hv;
                        if (t == sNobs[m] - 1) g_hout[sSamp[m] * HID + jh] = hv;
                    }
                }
                __syncthreads();   // publish hT(t)
            }
        }

        // ================= head (64 samples) =================
        float* sWts  = sm + O_WTS;
        float* sXcat = sm + O_XCAT;
        float* sWc2  = sm + O_WC2;
        float* sC1o  = sm + O_C1;

#pragma unroll
        for (int q = 0; q < 8; ++q) {
            int idx = q * NTHREADS + tid;
            int r = idx >> 5, cc = idx & 31;
            *(float4*)(sWts + r * 132 + cc * 4) = *(const float4*)(W_ts + r * HID + cc * 4);
        }
        for (int idx = tid; idx < NACT * 32; idx += NTHREADS) {
            int o = idx >> 5, kb = (idx & 31) * 4;
            *(float4*)(sWc2 + o * 132 + kb) = *(const float4*)(W_c2 + o * HID + kb);
        }
        __syncthreads();

        // x_OS = relu(s_OS @ W_os^T + b_os)
        {
            float wos[8];
#pragma unroll
            for (int i = 0; i < 8; ++i) wos[i] = W_os[jh * 8 + i];
            float bos = b_os[jh];
#pragma unroll
            for (int mm = 0; mm < 16; ++mm) {
                int m = mg * 16 + mm;
                const float4* sp = (const float4*)(s + sSamp[m] * SDIM);
                float4 s0 = sp[0], s1 = sp[1];
                float a = bos;
                a = fmaf(wos[0], s0.x, a); a = fmaf(wos[1], s0.y, a);
                a = fmaf(wos[2], s0.z, a); a = fmaf(wos[3], s0.w, a);
                a = fmaf(wos[4], s1.x, a); a = fmaf(wos[5], s1.y, a);
                a = fmaf(wos[6], s1.z, a); a = fmaf(wos[7], s1.w, a);
                sXcat[m * 256 + jh] = fmaxf(a, 0.0f);
            }
        }
        // x_TS = relu(hout @ W_ts^T + b_ts)
        {
            float a16[16];
#pragma unroll
            for (int mm = 0; mm < 16; ++mm) a16[mm] = 0.0f;
#pragma unroll 1
            for (int k4 = 0; k4 < 32; ++k4) {
                float4 w = *(const float4*)(sWts + jh * 132 + k4 * 4);
#pragma unroll
                for (int mm = 0; mm < 16; ++mm) {
                    int m = mg * 16 + mm;
                    float4 h = *(const float4*)(g_hout + sSamp[m] * HID + k4 * 4);
                    float a = a16[mm];
                    a = fmaf(w.x, h.x, a);
                    a = fmaf(w.y, h.y, a);
                    a = fmaf(w.z, h.z, a);
                    a = fmaf(w.w, h.w, a);
                    a16[mm] = a;
                }
            }
            float bts = b_ts[jh];
#pragma unroll
            for (int mm = 0; mm < 16; ++mm) {
                int m = mg * 16 + mm;
                sXcat[m * 256 + HID + jh] = fmaxf(a16[mm] + bts, 0.0f);
            }
        }
        __syncthreads();

        // c1 = relu(xcat @ W_c1^T + b_c1), two staged halves
        {
            float a16[16];
#pragma unroll
            for (int mm = 0; mm < 16; ++mm) a16[mm] = 0.0f;
#pragma unroll 1
            for (int half = 0; half < 2; ++half) {
                __syncthreads();
#pragma unroll
                for (int q = 0; q < 8; ++q) {
                    int idx = q * NTHREADS + tid;
                    int r = idx >> 5, cc = idx & 31;
                    *(float4*)(sWts + r * 132 + cc * 4) =
                        *(const float4*)(W_c1 + r * 256 + half * 128 + cc * 4);
                }
                __syncthreads();
#pragma unroll 1
                for (int k4 = 0; k4 < 32; ++k4) {
                    float4 w = *(const float4*)(sWts + jh * 132 + k4 * 4);
#pragma unroll
                    for (int mm = 0; mm < 16; ++mm) {
                        int m = mg * 16 + mm;
                        float4 x = *(const float4*)(sXcat + m * 256 + half * 128 + k4 * 4);
                        float a = a16[mm];
                        a = fmaf(w.x, x.x, a);
                        a = fmaf(w.y, x.y, a);
                        a = fmaf(w.z, x.z, a);
                        a = fmaf(w.w, x.w, a);
                        a16[mm] = a;
                    }
                }
            }
            __syncthreads();
            float bc1 = b_c1[jh];
#pragma unroll
            for (int mm = 0; mm < 16; ++mm) {
                int m = mg * 16 + mm;
                sC1o[m * 132 + jh] = fmaxf(a16[mm] + bc1, 0.0f);
            }
        }
        __syncthreads();

        // out = c1 @ W_c2^T + b_c2 (576 outputs)
        for (int idx = tid; idx < M_TILE * NACT; idx += NTHREADS) {
            int m = idx / NACT, o = idx - m * NACT;
            float a = b_c2[o];
#pragma unroll 1
            for (int k4 = 0; k4 < 32; ++k4) {
                float4 w = *(const float4*)(sWc2 + o * 132 + k4 * 4);
                float4 x = *(const float4*)(sC1o + m * 132 + k4 * 4);
                a = fmaf(w.x, x.x, a);
                a = fmaf(w.y, x.y, a);
                a = fmaf(w.z, x.z, a);
                a = fmaf(w.w, x.w, a);
            }
            out[sSamp[m] * NACT + o] = a;
        }
        // tile-loop top barrier guards smem reuse
    }
}

// ---------------- launch ----------------
extern "C" void kernel_launch(void* const* d_in, const int* in_sizes, int n_in,
                              void* d_out, int out_size) {
    const float* s    = (const float*)d_in[0];
    const float* W_os = (const float*)d_in[1];
    const float* b_os = (const float*)d_in[2];
    const float* W_ih = (const float*)d_in[3];
    const float* W_hh = (const float*)d_in[4];
    const float* b_ih = (const float*)d_in[5];
    const float* b_hh = (const float*)d_in[6];
    const float* W_ts = (const float*)d_in[7];
    const float* b_ts = (const float*)d_in[8];
    const float* W_c1 = (const float*)d_in[9];
    const float* b_c1 = (const float*)d_in[10];
    const float* W_c2 = (const float*)d_in[11];
    const float* b_c2 = (const float*)d_in[12];
    float* out = (float*)d_out;

    cudaFuncSetAttribute(k_main, cudaFuncAttributeMaxDynamicSharedMemorySize, SMEM_BYTES);

    k_count<<<B_TOT / 256, 256>>>(s);
    k_prefix<<<1, 1>>>();
    k_scatter<<<B_TOT / 256, 256>>>();
    k_main<<<NPERSIST, NTHREADS, SMEM_BYTES>>>(s, W_os, b_os, W_ih, W_hh, b_ih, b_hh,
                                               W_ts, b_ts, W_c1, b_c1, W_c2, b_c2, out);
}